// round 11
// baseline (speedup 1.0000x reference)
#include <cuda_runtime.h>
#include <cuda_fp16.h>
#include <cstdint>

#define dE 8
#define dH 1024
#define dI 4096
#define dN 2048
#define dK 2
#define dNK 4096

#define TBK 32
#define NTH 256

// smem: row stride 20 words (80B) — 16B-aligned rows for ldmatrix, conflict-free
#define AST 20

// ---- GEMM1 geometry: CTA 128x64, warp tile 32x32 (dual-matrix) ----
#define G1_TBM 128
#define G1_TBN 64
#define G1_AW (G1_TBM * AST)          // 2560 words per stage
#define G1_BW (G1_TBN * AST)          // 1280 words per stage

// ---- GEMM2 geometry: CTA 128x128, warp tile 32x64 ----
#define G2_TBM 128
#define G2_TBN 128
#define G2_AW (G2_TBM * AST)          // 2560
#define G2_BW (G2_TBN * AST)          // 2560

// ---- scratch (device globals; no runtime allocation) ----
__device__ int    g_pairs[dNK];
__device__ int    g_off[dE + 1];
__device__ __half g_h[(size_t)dNK * dI];   // SwiGLU hidden, fp16 (32 MB)

__device__ __forceinline__ uint32_t su32(const void* p) {
    return (uint32_t)__cvta_generic_to_shared(p);
}
__device__ __forceinline__ uint32_t packh2(float lo, float hi) {
    __half2 h = __floats2half2_rn(lo, hi);
    return *(uint32_t*)&h;
}
__device__ __forceinline__ void mma_f16(float* d, const uint32_t* a, const uint32_t* b) {
    asm volatile("mma.sync.aligned.m16n8k16.row.col.f32.f16.f16.f32 "
                 "{%0,%1,%2,%3}, {%4,%5,%6,%7}, {%8,%9}, {%0,%1,%2,%3};\n"
                 : "+f"(d[0]), "+f"(d[1]), "+f"(d[2]), "+f"(d[3])
                 : "r"(a[0]), "r"(a[1]), "r"(a[2]), "r"(a[3]),
                   "r"(b[0]), "r"(b[1]));
}
__device__ __forceinline__ void ldmx4(uint32_t* r, uint32_t addr) {
    asm volatile("ldmatrix.sync.aligned.m8n8.x4.shared.b16 {%0,%1,%2,%3}, [%4];"
                 : "=r"(r[0]), "=r"(r[1]), "=r"(r[2]), "=r"(r[3]) : "r"(addr));
}

// ---- routing: histogram + scan + scatter, single CTA ----
__global__ void route_kernel(const int* __restrict__ idx) {
    __shared__ int s_cnt[dE], s_base[dE];
    int t = threadIdx.x;
    if (t < dE) s_cnt[t] = 0;
    __syncthreads();
    for (int p = t; p < dNK; p += blockDim.x) atomicAdd(&s_cnt[idx[p]], 1);
    __syncthreads();
    if (t == 0) {
        int acc = 0;
        for (int e = 0; e < dE; ++e) { g_off[e] = acc; s_base[e] = acc; acc += s_cnt[e]; }
        g_off[dE] = acc;
    }
    __syncthreads();
    if (t < dE) s_cnt[t] = 0;
    __syncthreads();
    for (int p = t; p < dNK; p += blockDim.x) {
        int e = idx[p];
        int slot = s_base[e] + atomicAdd(&s_cnt[e], 1);
        g_pairs[slot] = p;
    }
}

// ---- zero the output (gemm2 accumulates into it atomically) ----
__global__ void zero_out_kernel(float* __restrict__ out) {
    int i = blockIdx.x * blockDim.x + threadIdx.x;
    if (i < dN * dH / 4) ((float4*)out)[i] = make_float4(0.f, 0.f, 0.f, 0.f);
}

// ============ GEMM1: CTA 128x64, warp 32x32 dual — h = silu(x@w1)*(x@w3) ============
__global__ void __launch_bounds__(NTH, 2)
gemm1_mma(const float* __restrict__ x,
          const float* __restrict__ w1,
          const float* __restrict__ w3) {
    const int e    = blockIdx.z;
    const int mEnd = g_off[e + 1];
    const int m0   = g_off[e] + blockIdx.x * G1_TBM;
    if (m0 >= mEnd) return;
    const int i0 = blockIdx.y * G1_TBN;

    __shared__ __align__(16) uint32_t dsm[2 * G1_AW + 4 * G1_BW];   // 40 KB
    __shared__ int s_tok[G1_TBM];

    const int t = threadIdx.x;
    const int w = t >> 5, l = t & 31;
    const int wm = w & 3, wn = w >> 2;
    const int lr = l >> 2, lc = l & 3;
    const uint32_t smb = su32(dsm);
    const int lmRow = l & 15;
    const int lmChk = (l >> 4) * 4;

    if (t < G1_TBM) { int s = m0 + t; s_tok[t] = (s < mEnd) ? g_pairs[s] / dK : -1; }
    __syncthreads();

    const float* w1e = w1 + (size_t)e * dH * dI + i0;
    const float* w3e = w3 + (size_t)e * dH * dI + i0;

    // A staging: 128 rows x 32k halfs -> 4 float4 per thread
    int aOffW[4];
    const float* aSrc[4];
    #pragma unroll
    for (int p = 0; p < 4; ++p) {
        int id = t + p * NTH;
        int row = id >> 3, ch = id & 7;
        aOffW[p] = row * AST + ch * 2;
        int tok = s_tok[row];
        aSrc[p] = x + (size_t)(tok < 0 ? 0 : tok) * dH + ch * 4;
    }
    // B staging: n = t&63, kb = (t>>6)*8
    const int bN = t & 63, bKb = (t >> 6) * 8;
    const int bOffW = bN * AST + (bKb >> 1);
    const float* b1Src = w1e + (size_t)bKb * dI + bN;
    const float* b3Src = w3e + (size_t)bKb * dI + bN;

    uint32_t uA[4][2], uB1[4], uB3[4];

    auto ldg_stage = [&](int kt) {
        const int k0 = kt * TBK;
        #pragma unroll
        for (int p = 0; p < 4; ++p) {
            float4 v = *(const float4*)(aSrc[p] + k0);
            uA[p][0] = packh2(v.x, v.y);
            uA[p][1] = packh2(v.z, v.w);
        }
        const float* pb1 = b1Src + (size_t)k0 * dI;
        const float* pb3 = b3Src + (size_t)k0 * dI;
        #pragma unroll
        for (int jj = 0; jj < 4; ++jj) {
            uB1[jj] = packh2(pb1[(size_t)(2 * jj) * dI], pb1[(size_t)(2 * jj + 1) * dI]);
            uB3[jj] = packh2(pb3[(size_t)(2 * jj) * dI], pb3[(size_t)(2 * jj + 1) * dI]);
        }
    };
    auto sts_stage = [&](int s) {
        #pragma unroll
        for (int p = 0; p < 4; ++p)
            *(uint2*)&dsm[s * G1_AW + aOffW[p]] = make_uint2(uA[p][0], uA[p][1]);
        *(uint4*)&dsm[2 * G1_AW + s * G1_BW + bOffW] =
            make_uint4(uB1[0], uB1[1], uB1[2], uB1[3]);
        *(uint4*)&dsm[2 * G1_AW + 2 * G1_BW + s * G1_BW + bOffW] =
            make_uint4(uB3[0], uB3[1], uB3[2], uB3[3]);
    };

    float accG[2][4][4] = {};
    float accU[2][4][4] = {};

    const int KT = dH / TBK;   // 32
    ldg_stage(0);
    sts_stage(0);
    __syncthreads();

    for (int kt = 0; kt < KT; ++kt) {
        const int s = kt & 1;
        if (kt + 1 < KT) ldg_stage(kt + 1);

        #pragma unroll
        for (int ks = 0; ks < 2; ++ks) {
            const int kw = ks * 8 + lmChk;
            uint32_t af[2][4];
            #pragma unroll
            for (int mi = 0; mi < 2; ++mi) {
                int r = wm * 32 + mi * 16 + lmRow;
                ldmx4(af[mi], smb + 4u * (uint32_t)(s * G1_AW + r * AST + kw));
            }
            uint32_t b1f[4][2], b3f[4][2];
            #pragma unroll
            for (int np = 0; np < 2; ++np) {
                int n = wn * 32 + np * 16 + lmRow;
                uint32_t q[4];
                ldmx4(q, smb + 4u * (uint32_t)(2 * G1_AW + s * G1_BW + n * AST + kw));
                b1f[np * 2][0] = q[0]; b1f[np * 2 + 1][0] = q[1];
                b1f[np * 2][1] = q[2]; b1f[np * 2 + 1][1] = q[3];
                ldmx4(q, smb + 4u * (uint32_t)(2 * G1_AW + 2 * G1_BW + s * G1_BW + n * AST + kw));
                b3f[np * 2][0] = q[0]; b3f[np * 2 + 1][0] = q[1];
                b3f[np * 2][1] = q[2]; b3f[np * 2 + 1][1] = q[3];
            }
            #pragma unroll
            for (int ni = 0; ni < 4; ++ni)
                #pragma unroll
                for (int mi = 0; mi < 2; ++mi) {
                    mma_f16(accG[mi][ni], af[mi], b1f[ni]);
                    mma_f16(accU[mi][ni], af[mi], b3f[ni]);
                }
        }

        if (kt + 1 < KT) sts_stage(s ^ 1);
        __syncthreads();
    }

    #pragma unroll
    for (int mi = 0; mi < 2; ++mi) {
        int r0 = m0 + wm * 32 + mi * 16 + lr;
        int r1 = r0 + 8;
        #pragma unroll
        for (int ni = 0; ni < 4; ++ni) {
            int c = i0 + wn * 32 + ni * 8 + lc * 2;
            if (r0 < mEnd) {
                float g0 = accG[mi][ni][0], g1 = accG[mi][ni][1];
                float u0 = accU[mi][ni][0], u1 = accU[mi][ni][1];
                float h0 = g0 / (1.0f + __expf(-g0)) * u0;
                float h1 = g1 / (1.0f + __expf(-g1)) * u1;
                *(uint32_t*)&g_h[(size_t)r0 * dI + c] = packh2(h0, h1);
            }
            if (r1 < mEnd) {
                float g2 = accG[mi][ni][2], g3 = accG[mi][ni][3];
                float u2 = accU[mi][ni][2], u3 = accU[mi][ni][3];
                float h2 = g2 / (1.0f + __expf(-g2)) * u2;
                float h3 = g3 / (1.0f + __expf(-g3)) * u3;
                *(uint32_t*)&g_h[(size_t)r1 * dI + c] = packh2(h2, h3);
            }
        }
    }
}

// ============ GEMM2: CTA 128x128, warp 32x64 — out += ew * (h @ w2) ============
__global__ void __launch_bounds__(NTH, 2)
gemm2_mma(const float* __restrict__ ew,
          const float* __restrict__ w2,
          float* __restrict__ out) {
    const int e    = blockIdx.z;
    const int mEnd = g_off[e + 1];
    const int m0   = g_off[e] + blockIdx.x * G2_TBM;
    if (m0 >= mEnd) return;
    const int h0 = blockIdx.y * G2_TBN;

    __shared__ __align__(16) uint32_t dsm[2 * G2_AW + 2 * G2_BW];   // 40 KB

    const int t = threadIdx.x;
    const int w = t >> 5, l = t & 31;
    const int wm = w & 3, wn = w >> 2;      // warp tile 32x64
    const int lr = l >> 2, lc = l & 3;
    const uint32_t smb = su32(dsm);
    const int lmRow = l & 15;
    const int lmChk = (l >> 4) * 4;

    const float* w2e = w2 + (size_t)e * dI * dH + h0;

    // A staging: 128 rows x 32k halfs -> 2 uint4 per thread
    int aOffW[2];
    const __half* aSrc[2];
    #pragma unroll
    for (int p = 0; p < 2; ++p) {
        int id = t + p * NTH;
        int row = id >> 2, qc = id & 3;
        aOffW[p] = row * AST + qc * 4;
        int grow = (m0 + row < mEnd) ? (m0 + row) : m0;
        aSrc[p] = g_h + (size_t)grow * dI + qc * 8;
    }
    // B staging: 128 n x 32 k: n = t&127, kb = (t>>7)*16 -> 16 floats, 8 words
    const int bN = t & 127, bKb = (t >> 7) * 16;
    const int bOffW = bN * AST + (bKb >> 1);
    const float* bSrc = w2e + (size_t)bKb * dH + bN;

    uint4 uA[2];
    uint32_t uB[8];

    auto ldg_stage = [&](int kt) {
        const int k0 = kt * TBK;
        #pragma unroll
        for (int p = 0; p < 2; ++p)
            uA[p] = *(const uint4*)(aSrc[p] + k0);
        const float* pb = bSrc + (size_t)k0 * dH;
        #pragma unroll
        for (int jj = 0; jj < 8; ++jj)
            uB[jj] = packh2(pb[(size_t)(2 * jj) * dH], pb[(size_t)(2 * jj + 1) * dH]);
    };
    auto sts_stage = [&](int s) {
        #pragma unroll
        for (int p = 0; p < 2; ++p)
            *(uint4*)&dsm[s * G2_AW + aOffW[p]] = uA[p];
        *(uint4*)&dsm[2 * G2_AW + s * G2_BW + bOffW] =
            make_uint4(uB[0], uB[1], uB[2], uB[3]);
        *(uint4*)&dsm[2 * G2_AW + s * G2_BW + bOffW + 4] =
            make_uint4(uB[4], uB[5], uB[6], uB[7]);
    };

    float acc[2][8][4] = {};

    const int KT = dI / TBK;   // 128
    ldg_stage(0);
    sts_stage(0);
    __syncthreads();

    for (int kt = 0; kt < KT; ++kt) {
        const int s = kt & 1;
        if (kt + 1 < KT) ldg_stage(kt + 1);

        #pragma unroll
        for (int ks = 0; ks < 2; ++ks) {
            const int kw = ks * 8 + lmChk;
            uint32_t af[2][4];
            #pragma unroll
            for (int mi = 0; mi < 2; ++mi) {
                int r = wm * 32 + mi * 16 + lmRow;
                ldmx4(af[mi], smb + 4u * (uint32_t)(s * G2_AW + r * AST + kw));
            }
            uint32_t bf[8][2];
            #pragma unroll
            for (int np = 0; np < 4; ++np) {
                int n = wn * 64 + np * 16 + lmRow;
                uint32_t q[4];
                ldmx4(q, smb + 4u * (uint32_t)(2 * G2_AW + s * G2_BW + n * AST + kw));
                bf[np * 2][0] = q[0]; bf[np * 2 + 1][0] = q[1];
                bf[np * 2][1] = q[2]; bf[np * 2 + 1][1] = q[3];
            }
            #pragma unroll
            for (int ni = 0; ni < 8; ++ni)
                #pragma unroll
                for (int mi = 0; mi < 2; ++mi)
                    mma_f16(acc[mi][ni], af[mi], bf[ni]);
        }

        if (kt + 1 < KT) sts_stage(s ^ 1);
        __syncthreads();
    }

    // fused epilogue: out[token] += ew * acc (exactly 2 adds per element)
    #pragma unroll
    for (int mi = 0; mi < 2; ++mi) {
        int r0 = m0 + wm * 32 + mi * 16 + lr;
        int r1 = r0 + 8;
        int tk0 = -1, tk1 = -1;
        float wg0 = 0.0f, wg1 = 0.0f;
        if (r0 < mEnd) { int p = g_pairs[r0]; wg0 = ew[p]; tk0 = p / dK; }
        if (r1 < mEnd) { int p = g_pairs[r1]; wg1 = ew[p]; tk1 = p / dK; }
        #pragma unroll
        for (int ni = 0; ni < 8; ++ni) {
            int c = h0 + wn * 64 + ni * 8 + lc * 2;
            if (tk0 >= 0) {
                atomicAdd(&out[(size_t)tk0 * dH + c],     wg0 * acc[mi][ni][0]);
                atomicAdd(&out[(size_t)tk0 * dH + c + 1], wg0 * acc[mi][ni][1]);
            }
            if (tk1 >= 0) {
                atomicAdd(&out[(size_t)tk1 * dH + c],     wg1 * acc[mi][ni][2]);
                atomicAdd(&out[(size_t)tk1 * dH + c + 1], wg1 * acc[mi][ni][3]);
            }
        }
    }
}

extern "C" void kernel_launch(void* const* d_in, const int* in_sizes, int n_in,
                              void* d_out, int out_size) {
    const float* x   = (const float*)d_in[0];
    const int*   idx = (const int*)  d_in[1];
    const float* ew  = (const float*)d_in[2];
    const float* w1  = (const float*)d_in[3];
    const float* w2  = (const float*)d_in[4];
    const float* w3  = (const float*)d_in[5];
    float* out = (float*)d_out;

    route_kernel<<<1, 256>>>(idx);
    zero_out_kernel<<<(dN * dH / 4 + 255) / 256, 256>>>(out);
    dim3 g1(dNK / G1_TBM, dI / G1_TBN, dE);   // 32 x 64 x 8
    gemm1_mma<<<g1, NTH>>>(x, w1, w3);
    dim3 g2(dNK / G2_TBM, dH / G2_TBN, dE);   // 32 x 8 x 8
    gemm2_mma<<<g2, NTH>>>(ew, w2, out);
}

// round 12
// speedup vs baseline: 1.4385x; 1.4385x over previous
#include <cuda_runtime.h>
#include <cuda_fp16.h>
#include <cstdint>

#define dE 8
#define dH 1024
#define dI 4096
#define dN 2048
#define dK 2
#define dNK 4096

#define TBK 32
#define NTH 256

// smem: row stride 20 words (80B) — 16B-aligned rows for ldmatrix, conflict-free
#define AST 20

// ---- GEMM1 geometry: CTA 128x64, warp tile 32x32 (dual-matrix) ----
#define G1_TBM 128
#define G1_TBN 64
#define G1_AW (G1_TBM * AST)
#define G1_BW (G1_TBN * AST)

// ---- GEMM2 geometry: CTA 128x128, warp tile 32x64 ----
#define G2_TBM 128
#define G2_TBN 128
#define G2_AW (G2_TBM * AST)
#define G2_BW (G2_TBN * AST)

// ---- scratch (device globals; no runtime allocation) ----
__device__ int    g_pairs[dNK];
__device__ int    g_off[dE + 1];
__device__ __half g_h[(size_t)dNK * dI];   // SwiGLU hidden, fp16 (32 MB)

__device__ __forceinline__ uint32_t su32(const void* p) {
    return (uint32_t)__cvta_generic_to_shared(p);
}
__device__ __forceinline__ uint32_t packh2(float lo, float hi) {
    __half2 h = __floats2half2_rn(lo, hi);
    return *(uint32_t*)&h;
}
__device__ __forceinline__ void mma_f16(float* d, const uint32_t* a, const uint32_t* b) {
    asm volatile("mma.sync.aligned.m16n8k16.row.col.f32.f16.f16.f32 "
                 "{%0,%1,%2,%3}, {%4,%5,%6,%7}, {%8,%9}, {%0,%1,%2,%3};\n"
                 : "+f"(d[0]), "+f"(d[1]), "+f"(d[2]), "+f"(d[3])
                 : "r"(a[0]), "r"(a[1]), "r"(a[2]), "r"(a[3]),
                   "r"(b[0]), "r"(b[1]));
}
__device__ __forceinline__ void ldmx4(uint32_t* r, uint32_t addr) {
    asm volatile("ldmatrix.sync.aligned.m8n8.x4.shared.b16 {%0,%1,%2,%3}, [%4];"
                 : "=r"(r[0]), "=r"(r[1]), "=r"(r[2]), "=r"(r[3]) : "r"(addr));
}
__device__ __forceinline__ void cpa16(uint32_t dst, const void* src) {
    asm volatile("cp.async.cg.shared.global [%0], [%1], 16;\n" :: "r"(dst), "l"(src));
}
__device__ __forceinline__ void cpa_commit() { asm volatile("cp.async.commit_group;\n"); }
__device__ __forceinline__ void cpa_wait0()  { asm volatile("cp.async.wait_group 0;\n"); }

// ---- routing: histogram + scan + scatter, single CTA ----
__global__ void route_kernel(const int* __restrict__ idx) {
    __shared__ int s_cnt[dE], s_base[dE];
    int t = threadIdx.x;
    if (t < dE) s_cnt[t] = 0;
    __syncthreads();
    for (int p = t; p < dNK; p += blockDim.x) atomicAdd(&s_cnt[idx[p]], 1);
    __syncthreads();
    if (t == 0) {
        int acc = 0;
        for (int e = 0; e < dE; ++e) { g_off[e] = acc; s_base[e] = acc; acc += s_cnt[e]; }
        g_off[dE] = acc;
    }
    __syncthreads();
    if (t < dE) s_cnt[t] = 0;
    __syncthreads();
    for (int p = t; p < dNK; p += blockDim.x) {
        int e = idx[p];
        int slot = s_base[e] + atomicAdd(&s_cnt[e], 1);
        g_pairs[slot] = p;
    }
}

// ---- zero the output (gemm2 accumulates into it atomically) ----
__global__ void zero_out_kernel(float* __restrict__ out) {
    int i = blockIdx.x * blockDim.x + threadIdx.x;
    if (i < dN * dH / 4) ((float4*)out)[i] = make_float4(0.f, 0.f, 0.f, 0.f);
}

// ============ GEMM1: CTA 128x64, warp 32x32 dual — h = silu(x@w1)*(x@w3) ============
__global__ void __launch_bounds__(NTH, 2)
gemm1_mma(const float* __restrict__ x,
          const float* __restrict__ w1,
          const float* __restrict__ w3) {
    const int e    = blockIdx.z;
    const int mEnd = g_off[e + 1];
    const int m0   = g_off[e] + blockIdx.x * G1_TBM;
    if (m0 >= mEnd) return;
    const int i0 = blockIdx.y * G1_TBN;

    __shared__ __align__(16) uint32_t dsm[2 * G1_AW + 4 * G1_BW];   // 40 KB
    __shared__ int s_tok[G1_TBM];

    const int t = threadIdx.x;
    const int w = t >> 5, l = t & 31;
    const int wm = w & 3, wn = w >> 2;
    const int lr = l >> 2, lc = l & 3;
    const uint32_t smb = su32(dsm);
    const int lmRow = l & 15;
    const int lmChk = (l >> 4) * 4;

    if (t < G1_TBM) { int s = m0 + t; s_tok[t] = (s < mEnd) ? g_pairs[s] / dK : -1; }
    __syncthreads();

    const float* w1e = w1 + (size_t)e * dH * dI + i0;
    const float* w3e = w3 + (size_t)e * dH * dI + i0;

    int aOffW[4];
    const float* aSrc[4];
    #pragma unroll
    for (int p = 0; p < 4; ++p) {
        int id = t + p * NTH;
        int row = id >> 3, ch = id & 7;
        aOffW[p] = row * AST + ch * 2;
        int tok = s_tok[row];
        aSrc[p] = x + (size_t)(tok < 0 ? 0 : tok) * dH + ch * 4;
    }
    const int bN = t & 63, bKb = (t >> 6) * 8;
    const int bOffW = bN * AST + (bKb >> 1);
    const float* b1Src = w1e + (size_t)bKb * dI + bN;
    const float* b3Src = w3e + (size_t)bKb * dI + bN;

    uint32_t uA[4][2], uB1[4], uB3[4];

    auto ldg_stage = [&](int kt) {
        const int k0 = kt * TBK;
        #pragma unroll
        for (int p = 0; p < 4; ++p) {
            float4 v = *(const float4*)(aSrc[p] + k0);
            uA[p][0] = packh2(v.x, v.y);
            uA[p][1] = packh2(v.z, v.w);
        }
        const float* pb1 = b1Src + (size_t)k0 * dI;
        const float* pb3 = b3Src + (size_t)k0 * dI;
        #pragma unroll
        for (int jj = 0; jj < 4; ++jj) {
            uB1[jj] = packh2(pb1[(size_t)(2 * jj) * dI], pb1[(size_t)(2 * jj + 1) * dI]);
            uB3[jj] = packh2(pb3[(size_t)(2 * jj) * dI], pb3[(size_t)(2 * jj + 1) * dI]);
        }
    };
    auto sts_stage = [&](int s) {
        #pragma unroll
        for (int p = 0; p < 4; ++p)
            *(uint2*)&dsm[s * G1_AW + aOffW[p]] = make_uint2(uA[p][0], uA[p][1]);
        *(uint4*)&dsm[2 * G1_AW + s * G1_BW + bOffW] =
            make_uint4(uB1[0], uB1[1], uB1[2], uB1[3]);
        *(uint4*)&dsm[2 * G1_AW + 2 * G1_BW + s * G1_BW + bOffW] =
            make_uint4(uB3[0], uB3[1], uB3[2], uB3[3]);
    };

    float accG[2][4][4] = {};
    float accU[2][4][4] = {};

    const int KT = dH / TBK;   // 32
    ldg_stage(0);
    sts_stage(0);
    __syncthreads();

    for (int kt = 0; kt < KT; ++kt) {
        const int s = kt & 1;
        if (kt + 1 < KT) ldg_stage(kt + 1);

        #pragma unroll
        for (int ks = 0; ks < 2; ++ks) {
            const int kw = ks * 8 + lmChk;
            uint32_t af[2][4];
            #pragma unroll
            for (int mi = 0; mi < 2; ++mi) {
                int r = wm * 32 + mi * 16 + lmRow;
                ldmx4(af[mi], smb + 4u * (uint32_t)(s * G1_AW + r * AST + kw));
            }
            uint32_t b1f[4][2], b3f[4][2];
            #pragma unroll
            for (int np = 0; np < 2; ++np) {
                int n = wn * 32 + np * 16 + lmRow;
                uint32_t q[4];
                ldmx4(q, smb + 4u * (uint32_t)(2 * G1_AW + s * G1_BW + n * AST + kw));
                b1f[np * 2][0] = q[0]; b1f[np * 2 + 1][0] = q[1];
                b1f[np * 2][1] = q[2]; b1f[np * 2 + 1][1] = q[3];
                ldmx4(q, smb + 4u * (uint32_t)(2 * G1_AW + 2 * G1_BW + s * G1_BW + n * AST + kw));
                b3f[np * 2][0] = q[0]; b3f[np * 2 + 1][0] = q[1];
                b3f[np * 2][1] = q[2]; b3f[np * 2 + 1][1] = q[3];
            }
            #pragma unroll
            for (int ni = 0; ni < 4; ++ni)
                #pragma unroll
                for (int mi = 0; mi < 2; ++mi) {
                    mma_f16(accG[mi][ni], af[mi], b1f[ni]);
                    mma_f16(accU[mi][ni], af[mi], b3f[ni]);
                }
        }

        if (kt + 1 < KT) sts_stage(s ^ 1);
        __syncthreads();
    }

    #pragma unroll
    for (int mi = 0; mi < 2; ++mi) {
        int r0 = m0 + wm * 32 + mi * 16 + lr;
        int r1 = r0 + 8;
        #pragma unroll
        for (int ni = 0; ni < 4; ++ni) {
            int c = i0 + wn * 32 + ni * 8 + lc * 2;
            if (r0 < mEnd) {
                float g0 = accG[mi][ni][0], g1 = accG[mi][ni][1];
                float u0 = accU[mi][ni][0], u1 = accU[mi][ni][1];
                float h0 = g0 / (1.0f + __expf(-g0)) * u0;
                float h1 = g1 / (1.0f + __expf(-g1)) * u1;
                *(uint32_t*)&g_h[(size_t)r0 * dI + c] = packh2(h0, h1);
            }
            if (r1 < mEnd) {
                float g2 = accG[mi][ni][2], g3 = accG[mi][ni][3];
                float u2 = accU[mi][ni][2], u3 = accU[mi][ni][3];
                float h2 = g2 / (1.0f + __expf(-g2)) * u2;
                float h3 = g3 / (1.0f + __expf(-g3)) * u3;
                *(uint32_t*)&g_h[(size_t)r1 * dI + c] = packh2(h2, h3);
            }
        }
    }
}

// ============ GEMM2: CTA 128x128, warp 32x64, A via cp.async — out += ew*(h@w2) ============
__global__ void __launch_bounds__(NTH, 2)
gemm2_mma(const float* __restrict__ ew,
          const float* __restrict__ w2,
          float* __restrict__ out) {
    const int e    = blockIdx.z;
    const int mEnd = g_off[e + 1];
    const int m0   = g_off[e] + blockIdx.x * G2_TBM;
    if (m0 >= mEnd) return;
    const int h0 = blockIdx.y * G2_TBN;

    __shared__ __align__(16) uint32_t dsm[2 * G2_AW + 2 * G2_BW];   // 40 KB

    const int t = threadIdx.x;
    const int w = t >> 5, l = t & 31;
    const int wm = w & 3, wn = w >> 2;      // warp tile 32x64
    const int lr = l >> 2, lc = l & 3;
    const uint32_t smb = su32(dsm);
    const int lmRow = l & 15;
    const int lmChk = (l >> 4) * 4;

    const float* w2e = w2 + (size_t)e * dI * dH + h0;

    // A staging via cp.async: 128 rows x 64B per stage -> 2x16B per thread
    uint32_t aDstW[2];
    const __half* aSrc[2];
    #pragma unroll
    for (int p = 0; p < 2; ++p) {
        int id = t + p * NTH;
        int row = id >> 2, qc = id & 3;
        aDstW[p] = (uint32_t)(row * AST + qc * 4);
        int grow = (m0 + row < mEnd) ? (m0 + row) : m0;
        aSrc[p] = g_h + (size_t)grow * dI + qc * 8;
    }
    const int bN = t & 127, bKb = (t >> 7) * 16;
    const int bOffW = bN * AST + (bKb >> 1);
    const float* bSrc = w2e + (size_t)bKb * dH + bN;

    uint32_t uB[8];

    auto cpa_stage = [&](int kt, int s) {
        const int k0 = kt * TBK;
        #pragma unroll
        for (int p = 0; p < 2; ++p)
            cpa16(smb + 4u * (s * G2_AW + aDstW[p]), aSrc[p] + k0);
    };
    auto ldgB_stage = [&](int kt) {
        const float* pb = bSrc + (size_t)(kt * TBK) * dH;
        #pragma unroll
        for (int jj = 0; jj < 8; ++jj)
            uB[jj] = packh2(pb[(size_t)(2 * jj) * dH], pb[(size_t)(2 * jj + 1) * dH]);
    };
    auto stsB_stage = [&](int s) {
        *(uint4*)&dsm[2 * G2_AW + s * G2_BW + bOffW] =
            make_uint4(uB[0], uB[1], uB[2], uB[3]);
        *(uint4*)&dsm[2 * G2_AW + s * G2_BW + bOffW + 4] =
            make_uint4(uB[4], uB[5], uB[6], uB[7]);
    };

    float acc[2][8][4] = {};

    const int KT = dI / TBK;   // 128
    cpa_stage(0, 0);
    cpa_commit();
    ldgB_stage(0);
    stsB_stage(0);
    cpa_wait0();
    __syncthreads();

    for (int kt = 0; kt < KT; ++kt) {
        const int s = kt & 1;
        if (kt + 1 < KT) {
            cpa_stage(kt + 1, s ^ 1);
            cpa_commit();
            ldgB_stage(kt + 1);
        }

        #pragma unroll
        for (int ks = 0; ks < 2; ++ks) {
            const int kw = ks * 8 + lmChk;
            uint32_t af[2][4];
            #pragma unroll
            for (int mi = 0; mi < 2; ++mi) {
                int r = wm * 32 + mi * 16 + lmRow;
                ldmx4(af[mi], smb + 4u * (uint32_t)(s * G2_AW + r * AST + kw));
            }
            uint32_t bf[8][2];
            #pragma unroll
            for (int np = 0; np < 4; ++np) {
                int n = wn * 64 + np * 16 + lmRow;
                uint32_t q[4];
                ldmx4(q, smb + 4u * (uint32_t)(2 * G2_AW + s * G2_BW + n * AST + kw));
                bf[np * 2][0] = q[0]; bf[np * 2 + 1][0] = q[1];
                bf[np * 2][1] = q[2]; bf[np * 2 + 1][1] = q[3];
            }
            #pragma unroll
            for (int ni = 0; ni < 8; ++ni)
                #pragma unroll
                for (int mi = 0; mi < 2; ++mi)
                    mma_f16(acc[mi][ni], af[mi], bf[ni]);
        }

        if (kt + 1 < KT) stsB_stage(s ^ 1);
        cpa_wait0();
        __syncthreads();
    }

    // fused epilogue: out[token] += ew * acc (exactly 2 adds per element)
    #pragma unroll
    for (int mi = 0; mi < 2; ++mi) {
        int r0 = m0 + wm * 32 + mi * 16 + lr;
        int r1 = r0 + 8;
        int tk0 = -1, tk1 = -1;
        float wg0 = 0.0f, wg1 = 0.0f;
        if (r0 < mEnd) { int p = g_pairs[r0]; wg0 = ew[p]; tk0 = p / dK; }
        if (r1 < mEnd) { int p = g_pairs[r1]; wg1 = ew[p]; tk1 = p / dK; }
        #pragma unroll
        for (int ni = 0; ni < 8; ++ni) {
            int c = h0 + wn * 64 + ni * 8 + lc * 2;
            if (tk0 >= 0) {
                atomicAdd(&out[(size_t)tk0 * dH + c],     wg0 * acc[mi][ni][0]);
                atomicAdd(&out[(size_t)tk0 * dH + c + 1], wg0 * acc[mi][ni][1]);
            }
            if (tk1 >= 0) {
                atomicAdd(&out[(size_t)tk1 * dH + c],     wg1 * acc[mi][ni][2]);
                atomicAdd(&out[(size_t)tk1 * dH + c + 1], wg1 * acc[mi][ni][3]);
            }
        }
    }
}

extern "C" void kernel_launch(void* const* d_in, const int* in_sizes, int n_in,
                              void* d_out, int out_size) {
    const float* x   = (const float*)d_in[0];
    const int*   idx = (const int*)  d_in[1];
    const float* ew  = (const float*)d_in[2];
    const float* w1  = (const float*)d_in[3];
    const float* w2  = (const float*)d_in[4];
    const float* w3  = (const float*)d_in[5];
    float* out = (float*)d_out;

    route_kernel<<<1, 256>>>(idx);
    zero_out_kernel<<<(dN * dH / 4 + 255) / 256, 256>>>(out);
    dim3 g1(dNK / G1_TBM, dI / G1_TBN, dE);   // 32 x 64 x 8
    gemm1_mma<<<g1, NTH>>>(x, w1, w3);
    dim3 g2(dNK / G2_TBM, dH / G2_TBN, dE);   // 32 x 8 x 8
    gemm2_mma<<<g2, NTH>>>(ew, w2, out);
}

// round 13
// speedup vs baseline: 1.4749x; 1.0253x over previous
#include <cuda_runtime.h>
#include <cuda_fp16.h>
#include <cstdint>

#define dE 8
#define dH 1024
#define dI 4096
#define dN 2048
#define dK 2
#define dNK 4096

#define TBK 64
#define NTH 256

// smem: row stride 36 words (144B) — 16B-aligned rows for ldmatrix; 36r mod 32
// = 4r mod 32 distinct for any 8 consecutive rows -> conflict-free ldmatrix
#define AST 36

// ---- GEMM1 geometry: CTA 128x64, warp tile 32x32 (dual-matrix) ----
#define G1_TBM 128
#define G1_TBN 64
#define G1_AW (G1_TBM * AST)          // 4608 words per stage
#define G1_BW (G1_TBN * AST)          // 2304 words per stage
#define G1_SMEM_W (2 * G1_AW + 4 * G1_BW)   // 18432 words = 72 KB

// ---- GEMM2 geometry: CTA 128x128, warp tile 32x64 ----
#define G2_TBM 128
#define G2_TBN 128
#define G2_AW (G2_TBM * AST)          // 4608
#define G2_BW (G2_TBN * AST)          // 4608
#define G2_SMEM_W (2 * G2_AW + 2 * G2_BW)   // 18432 words = 72 KB

// ---- scratch (device globals; no runtime allocation) ----
__device__ int    g_pairs[dNK];
__device__ int    g_off[dE + 1];
__device__ __half g_h[(size_t)dNK * dI];   // SwiGLU hidden, fp16 (32 MB)

__device__ __forceinline__ uint32_t su32(const void* p) {
    return (uint32_t)__cvta_generic_to_shared(p);
}
__device__ __forceinline__ uint32_t packh2(float lo, float hi) {
    __half2 h = __floats2half2_rn(lo, hi);
    return *(uint32_t*)&h;
}
__device__ __forceinline__ void mma_f16(float* d, const uint32_t* a, const uint32_t* b) {
    asm volatile("mma.sync.aligned.m16n8k16.row.col.f32.f16.f16.f32 "
                 "{%0,%1,%2,%3}, {%4,%5,%6,%7}, {%8,%9}, {%0,%1,%2,%3};\n"
                 : "+f"(d[0]), "+f"(d[1]), "+f"(d[2]), "+f"(d[3])
                 : "r"(a[0]), "r"(a[1]), "r"(a[2]), "r"(a[3]),
                   "r"(b[0]), "r"(b[1]));
}
__device__ __forceinline__ void ldmx4(uint32_t* r, uint32_t addr) {
    asm volatile("ldmatrix.sync.aligned.m8n8.x4.shared.b16 {%0,%1,%2,%3}, [%4];"
                 : "=r"(r[0]), "=r"(r[1]), "=r"(r[2]), "=r"(r[3]) : "r"(addr));
}
__device__ __forceinline__ void cpa16(uint32_t dst, const void* src) {
    asm volatile("cp.async.cg.shared.global [%0], [%1], 16;\n" :: "r"(dst), "l"(src));
}
__device__ __forceinline__ void cpa_commit() { asm volatile("cp.async.commit_group;\n"); }
__device__ __forceinline__ void cpa_wait0()  { asm volatile("cp.async.wait_group 0;\n"); }

// ---- routing: histogram + scan + scatter, single CTA ----
__global__ void route_kernel(const int* __restrict__ idx) {
    __shared__ int s_cnt[dE], s_base[dE];
    int t = threadIdx.x;
    if (t < dE) s_cnt[t] = 0;
    __syncthreads();
    for (int p = t; p < dNK; p += blockDim.x) atomicAdd(&s_cnt[idx[p]], 1);
    __syncthreads();
    if (t == 0) {
        int acc = 0;
        for (int e = 0; e < dE; ++e) { g_off[e] = acc; s_base[e] = acc; acc += s_cnt[e]; }
        g_off[dE] = acc;
    }
    __syncthreads();
    if (t < dE) s_cnt[t] = 0;
    __syncthreads();
    for (int p = t; p < dNK; p += blockDim.x) {
        int e = idx[p];
        int slot = s_base[e] + atomicAdd(&s_cnt[e], 1);
        g_pairs[slot] = p;
    }
}

// ---- zero the output (gemm2 accumulates into it atomically) ----
__global__ void zero_out_kernel(float* __restrict__ out) {
    int i = blockIdx.x * blockDim.x + threadIdx.x;
    if (i < dN * dH / 4) ((float4*)out)[i] = make_float4(0.f, 0.f, 0.f, 0.f);
}

// ============ GEMM1: CTA 128x64, warp 32x32 dual, k64 — h = silu(x@w1)*(x@w3) ============
__global__ void __launch_bounds__(NTH, 2)
gemm1_mma(const float* __restrict__ x,
          const float* __restrict__ w1,
          const float* __restrict__ w3) {
    const int e    = blockIdx.z;
    const int mEnd = g_off[e + 1];
    const int m0   = g_off[e] + blockIdx.x * G1_TBM;
    if (m0 >= mEnd) return;
    const int i0 = blockIdx.y * G1_TBN;

    extern __shared__ uint32_t dsm[];
    __shared__ int s_tok[G1_TBM];

    const int t = threadIdx.x;
    const int w = t >> 5, l = t & 31;
    const int wm = w & 3, wn = w >> 2;
    const int lr = l >> 2, lc = l & 3;
    const uint32_t smb = su32(dsm);
    const int lmRow = l & 15;
    const int lmChk = (l >> 4) * 4;

    if (t < G1_TBM) { int s = m0 + t; s_tok[t] = (s < mEnd) ? g_pairs[s] / dK : -1; }
    __syncthreads();

    const float* w1e = w1 + (size_t)e * dH * dI + i0;
    const float* w3e = w3 + (size_t)e * dH * dI + i0;

    // A staging: 128 rows x 64k halfs -> 8 float4 per thread
    int aOffW[8];
    const float* aSrc[8];
    #pragma unroll
    for (int p = 0; p < 8; ++p) {
        int id = t + p * NTH;
        int row = id >> 4, ch = id & 15;
        aOffW[p] = row * AST + ch * 2;
        int tok = s_tok[row];
        aSrc[p] = x + (size_t)(tok < 0 ? 0 : tok) * dH + ch * 4;
    }
    // B staging: n = t&63, k-octet = t>>6 -> covers k 0..31 per half
    const int bN = t & 63, bKb = (t >> 6) * 8;
    const int bOffW = bN * AST + (bKb >> 1);
    const float* b1Src = w1e + (size_t)bKb * dI + bN;
    const float* b3Src = w3e + (size_t)bKb * dI + bN;

    uint32_t uA[8][2], uB1[4], uB3[4];

    auto ldgA = [&](int kt) {
        const int k0 = kt * TBK;
        #pragma unroll
        for (int p = 0; p < 8; ++p) {
            float4 v = *(const float4*)(aSrc[p] + k0);
            uA[p][0] = packh2(v.x, v.y);
            uA[p][1] = packh2(v.z, v.w);
        }
    };
    auto stsA = [&](int s) {
        #pragma unroll
        for (int p = 0; p < 8; ++p)
            *(uint2*)&dsm[s * G1_AW + aOffW[p]] = make_uint2(uA[p][0], uA[p][1]);
    };
    auto ldgB = [&](int kt, int h) {
        const float* pb1 = b1Src + (size_t)(kt * TBK + h * 32) * dI;
        const float* pb3 = b3Src + (size_t)(kt * TBK + h * 32) * dI;
        #pragma unroll
        for (int jj = 0; jj < 4; ++jj) {
            uB1[jj] = packh2(pb1[(size_t)(2 * jj) * dI], pb1[(size_t)(2 * jj + 1) * dI]);
            uB3[jj] = packh2(pb3[(size_t)(2 * jj) * dI], pb3[(size_t)(2 * jj + 1) * dI]);
        }
    };
    auto stsB = [&](int s, int h) {
        *(uint4*)&dsm[2 * G1_AW + s * G1_BW + bOffW + h * 16] =
            make_uint4(uB1[0], uB1[1], uB1[2], uB1[3]);
        *(uint4*)&dsm[2 * G1_AW + 2 * G1_BW + s * G1_BW + bOffW + h * 16] =
            make_uint4(uB3[0], uB3[1], uB3[2], uB3[3]);
    };

    auto compute_ks = [&](int s, int ks, float accG[2][4][4], float accU[2][4][4]) {
        const int kw = ks * 8 + lmChk;
        uint32_t af[2][4];
        #pragma unroll
        for (int mi = 0; mi < 2; ++mi) {
            int r = wm * 32 + mi * 16 + lmRow;
            ldmx4(af[mi], smb + 4u * (uint32_t)(s * G1_AW + r * AST + kw));
        }
        uint32_t b1f[4][2], b3f[4][2];
        #pragma unroll
        for (int np = 0; np < 2; ++np) {
            int n = wn * 32 + np * 16 + lmRow;
            uint32_t q[4];
            ldmx4(q, smb + 4u * (uint32_t)(2 * G1_AW + s * G1_BW + n * AST + kw));
            b1f[np * 2][0] = q[0]; b1f[np * 2 + 1][0] = q[1];
            b1f[np * 2][1] = q[2]; b1f[np * 2 + 1][1] = q[3];
            ldmx4(q, smb + 4u * (uint32_t)(2 * G1_AW + 2 * G1_BW + s * G1_BW + n * AST + kw));
            b3f[np * 2][0] = q[0]; b3f[np * 2 + 1][0] = q[1];
            b3f[np * 2][1] = q[2]; b3f[np * 2 + 1][1] = q[3];
        }
        #pragma unroll
        for (int ni = 0; ni < 4; ++ni)
            #pragma unroll
            for (int mi = 0; mi < 2; ++mi) {
                mma_f16(accG[mi][ni], af[mi], b1f[ni]);
                mma_f16(accU[mi][ni], af[mi], b3f[ni]);
            }
    };

    float accG[2][4][4] = {};
    float accU[2][4][4] = {};

    const int KT = dH / TBK;   // 16
    ldgA(0); stsA(0);
    ldgB(0, 0); stsB(0, 0);
    ldgB(0, 1); stsB(0, 1);
    __syncthreads();

    for (int kt = 0; kt < KT; ++kt) {
        const int s = kt & 1;
        const bool more = (kt + 1 < KT);
        if (more) { ldgA(kt + 1); ldgB(kt + 1, 0); }

        compute_ks(s, 0, accG, accU);
        compute_ks(s, 1, accG, accU);

        if (more) { stsB(s ^ 1, 0); ldgB(kt + 1, 1); }

        compute_ks(s, 2, accG, accU);
        compute_ks(s, 3, accG, accU);

        if (more) { stsA(s ^ 1); stsB(s ^ 1, 1); }
        __syncthreads();
    }

    #pragma unroll
    for (int mi = 0; mi < 2; ++mi) {
        int r0 = m0 + wm * 32 + mi * 16 + lr;
        int r1 = r0 + 8;
        #pragma unroll
        for (int ni = 0; ni < 4; ++ni) {
            int c = i0 + wn * 32 + ni * 8 + lc * 2;
            if (r0 < mEnd) {
                float g0 = accG[mi][ni][0], g1 = accG[mi][ni][1];
                float u0 = accU[mi][ni][0], u1 = accU[mi][ni][1];
                float h0 = g0 / (1.0f + __expf(-g0)) * u0;
                float h1 = g1 / (1.0f + __expf(-g1)) * u1;
                *(uint32_t*)&g_h[(size_t)r0 * dI + c] = packh2(h0, h1);
            }
            if (r1 < mEnd) {
                float g2 = accG[mi][ni][2], g3 = accG[mi][ni][3];
                float u2 = accU[mi][ni][2], u3 = accU[mi][ni][3];
                float h2 = g2 / (1.0f + __expf(-g2)) * u2;
                float h3 = g3 / (1.0f + __expf(-g3)) * u3;
                *(uint32_t*)&g_h[(size_t)r1 * dI + c] = packh2(h2, h3);
            }
        }
    }
}

// ============ GEMM2: CTA 128x128, warp 32x64, k64, A via cp.async — out += ew*(h@w2) ============
__global__ void __launch_bounds__(NTH, 2)
gemm2_mma(const float* __restrict__ ew,
          const float* __restrict__ w2,
          float* __restrict__ out) {
    const int e    = blockIdx.z;
    const int mEnd = g_off[e + 1];
    const int m0   = g_off[e] + blockIdx.x * G2_TBM;
    if (m0 >= mEnd) return;
    const int h0 = blockIdx.y * G2_TBN;

    extern __shared__ uint32_t dsm[];

    const int t = threadIdx.x;
    const int w = t >> 5, l = t & 31;
    const int wm = w & 3, wn = w >> 2;      // warp tile 32x64
    const int lr = l >> 2, lc = l & 3;
    const uint32_t smb = su32(dsm);
    const int lmRow = l & 15;
    const int lmChk = (l >> 4) * 4;

    const float* w2e = w2 + (size_t)e * dI * dH + h0;

    // A staging via cp.async: 128 rows x 128B per stage -> 4x16B per thread
    uint32_t aDstW[4];
    const __half* aSrc[4];
    #pragma unroll
    for (int p = 0; p < 4; ++p) {
        int id = t + p * NTH;
        int row = id >> 3, qc = id & 7;
        aDstW[p] = (uint32_t)(row * AST + qc * 4);
        int grow = (m0 + row < mEnd) ? (m0 + row) : m0;
        aSrc[p] = g_h + (size_t)grow * dI + qc * 8;
    }
    // B staging: n = t&127, 16 k's per thread per half
    const int bN = t & 127, bKb = (t >> 7) * 16;
    const int bOffW = bN * AST + (bKb >> 1);
    const float* bSrc = w2e + (size_t)bKb * dH + bN;

    uint32_t uB[8];

    auto cpaA = [&](int kt, int s) {
        const int k0 = kt * TBK;
        #pragma unroll
        for (int p = 0; p < 4; ++p)
            cpa16(smb + 4u * (s * G2_AW + aDstW[p]), aSrc[p] + k0);
    };
    auto ldgB = [&](int kt, int h) {
        const float* pb = bSrc + (size_t)(kt * TBK + h * 32) * dH;
        #pragma unroll
        for (int jj = 0; jj < 8; ++jj)
            uB[jj] = packh2(pb[(size_t)(2 * jj) * dH], pb[(size_t)(2 * jj + 1) * dH]);
    };
    auto stsB = [&](int s, int h) {
        *(uint4*)&dsm[2 * G2_AW + s * G2_BW + bOffW + h * 16] =
            make_uint4(uB[0], uB[1], uB[2], uB[3]);
        *(uint4*)&dsm[2 * G2_AW + s * G2_BW + bOffW + h * 16 + 4] =
            make_uint4(uB[4], uB[5], uB[6], uB[7]);
    };

    float acc[2][8][4] = {};

    auto compute_ks = [&](int s, int ks) {
        const int kw = ks * 8 + lmChk;
        uint32_t af[2][4];
        #pragma unroll
        for (int mi = 0; mi < 2; ++mi) {
            int r = wm * 32 + mi * 16 + lmRow;
            ldmx4(af[mi], smb + 4u * (uint32_t)(s * G2_AW + r * AST + kw));
        }
        uint32_t bf[8][2];
        #pragma unroll
        for (int np = 0; np < 4; ++np) {
            int n = wn * 64 + np * 16 + lmRow;
            uint32_t q[4];
            ldmx4(q, smb + 4u * (uint32_t)(2 * G2_AW + s * G2_BW + n * AST + kw));
            bf[np * 2][0] = q[0]; bf[np * 2 + 1][0] = q[1];
            bf[np * 2][1] = q[2]; bf[np * 2 + 1][1] = q[3];
        }
        #pragma unroll
        for (int ni = 0; ni < 8; ++ni)
            #pragma unroll
            for (int mi = 0; mi < 2; ++mi)
                mma_f16(acc[mi][ni], af[mi], bf[ni]);
    };

    const int KT = dI / TBK;   // 64
    cpaA(0, 0); cpa_commit();
    ldgB(0, 0); stsB(0, 0);
    ldgB(0, 1); stsB(0, 1);
    cpa_wait0();
    __syncthreads();

    for (int kt = 0; kt < KT; ++kt) {
        const int s = kt & 1;
        const bool more = (kt + 1 < KT);
        if (more) { cpaA(kt + 1, s ^ 1); cpa_commit(); ldgB(kt + 1, 0); }

        compute_ks(s, 0);
        compute_ks(s, 1);

        if (more) { stsB(s ^ 1, 0); ldgB(kt + 1, 1); }

        compute_ks(s, 2);
        compute_ks(s, 3);

        if (more) stsB(s ^ 1, 1);
        cpa_wait0();
        __syncthreads();
    }

    // fused epilogue: out[token] += ew * acc (exactly 2 adds per element)
    #pragma unroll
    for (int mi = 0; mi < 2; ++mi) {
        int r0 = m0 + wm * 32 + mi * 16 + lr;
        int r1 = r0 + 8;
        int tk0 = -1, tk1 = -1;
        float wg0 = 0.0f, wg1 = 0.0f;
        if (r0 < mEnd) { int p = g_pairs[r0]; wg0 = ew[p]; tk0 = p / dK; }
        if (r1 < mEnd) { int p = g_pairs[r1]; wg1 = ew[p]; tk1 = p / dK; }
        #pragma unroll
        for (int ni = 0; ni < 8; ++ni) {
            int c = h0 + wn * 64 + ni * 8 + lc * 2;
            if (tk0 >= 0) {
                atomicAdd(&out[(size_t)tk0 * dH + c],     wg0 * acc[mi][ni][0]);
                atomicAdd(&out[(size_t)tk0 * dH + c + 1], wg0 * acc[mi][ni][1]);
            }
            if (tk1 >= 0) {
                atomicAdd(&out[(size_t)tk1 * dH + c],     wg1 * acc[mi][ni][2]);
                atomicAdd(&out[(size_t)tk1 * dH + c + 1], wg1 * acc[mi][ni][3]);
            }
        }
    }
}

extern "C" void kernel_launch(void* const* d_in, const int* in_sizes, int n_in,
                              void* d_out, int out_size) {
    const float* x   = (const float*)d_in[0];
    const int*   idx = (const int*)  d_in[1];
    const float* ew  = (const float*)d_in[2];
    const float* w1  = (const float*)d_in[3];
    const float* w2  = (const float*)d_in[4];
    const float* w3  = (const float*)d_in[5];
    float* out = (float*)d_out;

    const int smem1 = G1_SMEM_W * 4;   // 73728 B
    const int smem2 = G2_SMEM_W * 4;   // 73728 B
    cudaFuncSetAttribute(gemm1_mma, cudaFuncAttributeMaxDynamicSharedMemorySize, smem1);
    cudaFuncSetAttribute(gemm2_mma, cudaFuncAttributeMaxDynamicSharedMemorySize, smem2);

    route_kernel<<<1, 256>>>(idx);
    zero_out_kernel<<<(dN * dH / 4 + 255) / 256, 256>>>(out);
    dim3 g1(dNK / G1_TBM, dI / G1_TBN, dE);   // 32 x 64 x 8
    gemm1_mma<<<g1, NTH, smem1>>>(x, w1, w3);
    dim3 g2(dNK / G2_TBM, dH / G2_TBN, dE);   // 32 x 8 x 8
    gemm2_mma<<<g2, NTH, smem2>>>(ew, w2, out);
}

// round 14
// speedup vs baseline: 1.6136x; 1.0940x over previous
#include <cuda_runtime.h>
#include <cuda_fp16.h>
#include <cstdint>

#define dE 8
#define dH 1024
#define dI 4096
#define dN 2048
#define dK 2
#define dNK 4096

#define TBK 64
#define NTH 256

// smem: row stride 36 words (144B) — 16B-aligned rows for ldmatrix; conflict-free
#define AST 36

// ---- GEMM1 geometry: CTA 128x64, warp tile 32x32 (dual-matrix) ----
#define G1_TBM 128
#define G1_TBN 64
#define G1_AW (G1_TBM * AST)
#define G1_BW (G1_TBN * AST)
#define G1_SMEM_W (2 * G1_AW + 4 * G1_BW)   // 72 KB

// ---- GEMM2 geometry: CTA 128x128, warp tile 32x64 ----
#define G2_TBM 128
#define G2_TBN 128
#define G2_AW (G2_TBM * AST)
#define G2_BW (G2_TBN * AST)
#define G2_SMEM_W (2 * G2_AW + 2 * G2_BW)   // 72 KB

// ---- scratch (device globals; no runtime allocation) ----
__device__ int    g_pairs[dNK];
__device__ int    g_off[dE + 1];
__device__ __half g_x[(size_t)dN * dH];    // x in fp16 (4 MB, L2-resident)
__device__ __half g_h[(size_t)dNK * dI];   // SwiGLU hidden, fp16 (32 MB)

__device__ __forceinline__ uint32_t su32(const void* p) {
    return (uint32_t)__cvta_generic_to_shared(p);
}
__device__ __forceinline__ uint32_t packh2(float lo, float hi) {
    __half2 h = __floats2half2_rn(lo, hi);
    return *(uint32_t*)&h;
}
__device__ __forceinline__ void mma_f16(float* d, const uint32_t* a, const uint32_t* b) {
    asm volatile("mma.sync.aligned.m16n8k16.row.col.f32.f16.f16.f32 "
                 "{%0,%1,%2,%3}, {%4,%5,%6,%7}, {%8,%9}, {%0,%1,%2,%3};\n"
                 : "+f"(d[0]), "+f"(d[1]), "+f"(d[2]), "+f"(d[3])
                 : "r"(a[0]), "r"(a[1]), "r"(a[2]), "r"(a[3]),
                   "r"(b[0]), "r"(b[1]));
}
__device__ __forceinline__ void ldmx4(uint32_t* r, uint32_t addr) {
    asm volatile("ldmatrix.sync.aligned.m8n8.x4.shared.b16 {%0,%1,%2,%3}, [%4];"
                 : "=r"(r[0]), "=r"(r[1]), "=r"(r[2]), "=r"(r[3]) : "r"(addr));
}
__device__ __forceinline__ void cpa16(uint32_t dst, const void* src) {
    asm volatile("cp.async.cg.shared.global [%0], [%1], 16;\n" :: "r"(dst), "l"(src));
}
__device__ __forceinline__ void cpa_commit() { asm volatile("cp.async.commit_group;\n"); }
__device__ __forceinline__ void cpa_wait0()  { asm volatile("cp.async.wait_group 0;\n"); }

// ---- routing: histogram + scan + scatter, single CTA ----
__global__ void route_kernel(const int* __restrict__ idx) {
    __shared__ int s_cnt[dE], s_base[dE];
    int t = threadIdx.x;
    if (t < dE) s_cnt[t] = 0;
    __syncthreads();
    for (int p = t; p < dNK; p += blockDim.x) atomicAdd(&s_cnt[idx[p]], 1);
    __syncthreads();
    if (t == 0) {
        int acc = 0;
        for (int e = 0; e < dE; ++e) { g_off[e] = acc; s_base[e] = acc; acc += s_cnt[e]; }
        g_off[dE] = acc;
    }
    __syncthreads();
    if (t < dE) s_cnt[t] = 0;
    __syncthreads();
    for (int p = t; p < dNK; p += blockDim.x) {
        int e = idx[p];
        int slot = s_base[e] + atomicAdd(&s_cnt[e], 1);
        g_pairs[slot] = p;
    }
}

// ---- zero out + convert x -> fp16 ----
__global__ void zero_out_kernel(float* __restrict__ out) {
    int i = blockIdx.x * blockDim.x + threadIdx.x;
    if (i < dN * dH / 4) ((float4*)out)[i] = make_float4(0.f, 0.f, 0.f, 0.f);
}
__global__ void cvt_x_kernel(const float* __restrict__ x) {
    int i = blockIdx.x * blockDim.x + threadIdx.x;   // over N*H/4
    if (i >= dN * dH / 4) return;
    float4 v = ((const float4*)x)[i];
    uint2 o = make_uint2(packh2(v.x, v.y), packh2(v.z, v.w));
    *(uint2*)&g_x[(size_t)i * 4] = o;
}

// ============ GEMM1: CTA 128x64, warp 32x32 dual, k64, A via cp.async ============
__global__ void __launch_bounds__(NTH, 2)
gemm1_mma(const float* __restrict__ w1,
          const float* __restrict__ w3) {
    const int e    = blockIdx.z;
    const int mEnd = g_off[e + 1];
    const int m0   = g_off[e] + blockIdx.x * G1_TBM;
    if (m0 >= mEnd) return;
    const int i0 = blockIdx.y * G1_TBN;

    extern __shared__ uint32_t dsm[];
    __shared__ int s_tok[G1_TBM];

    const int t = threadIdx.x;
    const int w = t >> 5, l = t & 31;
    const int wm = w & 3, wn = w >> 2;
    const int lr = l >> 2, lc = l & 3;
    const uint32_t smb = su32(dsm);
    const int lmRow = l & 15;
    const int lmChk = (l >> 4) * 4;

    if (t < G1_TBM) { int s = m0 + t; s_tok[t] = (s < mEnd) ? g_pairs[s] / dK : -1; }
    __syncthreads();

    const float* w1e = w1 + (size_t)e * dH * dI + i0;
    const float* w3e = w3 + (size_t)e * dH * dI + i0;

    // A staging via cp.async: 128 rows x 128B per stage -> 4x16B per thread
    uint32_t aDstW[4];
    const __half* aSrc[4];
    #pragma unroll
    for (int p = 0; p < 4; ++p) {
        int id = t + p * NTH;
        int row = id >> 3, ch = id & 7;
        aDstW[p] = (uint32_t)(row * AST + ch * 4);
        int tok = s_tok[row];
        aSrc[p] = g_x + (size_t)(tok < 0 ? 0 : tok) * dH + ch * 8;
    }
    // B staging: n = t&63, k-octet = t>>6
    const int bN = t & 63, bKb = (t >> 6) * 8;
    const int bOffW = bN * AST + (bKb >> 1);
    const float* b1Src = w1e + (size_t)bKb * dI + bN;
    const float* b3Src = w3e + (size_t)bKb * dI + bN;

    uint32_t uB1[4], uB3[4];

    auto cpaA = [&](int kt, int s) {
        const int k0 = kt * TBK;
        #pragma unroll
        for (int p = 0; p < 4; ++p)
            cpa16(smb + 4u * (s * G1_AW + aDstW[p]), aSrc[p] + k0);
    };
    auto ldgB = [&](int kt, int h) {
        const float* pb1 = b1Src + (size_t)(kt * TBK + h * 32) * dI;
        const float* pb3 = b3Src + (size_t)(kt * TBK + h * 32) * dI;
        #pragma unroll
        for (int jj = 0; jj < 4; ++jj) {
            uB1[jj] = packh2(pb1[(size_t)(2 * jj) * dI], pb1[(size_t)(2 * jj + 1) * dI]);
            uB3[jj] = packh2(pb3[(size_t)(2 * jj) * dI], pb3[(size_t)(2 * jj + 1) * dI]);
        }
    };
    auto stsB = [&](int s, int h) {
        *(uint4*)&dsm[2 * G1_AW + s * G1_BW + bOffW + h * 16] =
            make_uint4(uB1[0], uB1[1], uB1[2], uB1[3]);
        *(uint4*)&dsm[2 * G1_AW + 2 * G1_BW + s * G1_BW + bOffW + h * 16] =
            make_uint4(uB3[0], uB3[1], uB3[2], uB3[3]);
    };

    float accG[2][4][4] = {};
    float accU[2][4][4] = {};

    auto compute_ks = [&](int s, int ks) {
        const int kw = ks * 8 + lmChk;
        uint32_t af[2][4];
        #pragma unroll
        for (int mi = 0; mi < 2; ++mi) {
            int r = wm * 32 + mi * 16 + lmRow;
            ldmx4(af[mi], smb + 4u * (uint32_t)(s * G1_AW + r * AST + kw));
        }
        uint32_t b1f[4][2], b3f[4][2];
        #pragma unroll
        for (int np = 0; np < 2; ++np) {
            int n = wn * 32 + np * 16 + lmRow;
            uint32_t q[4];
            ldmx4(q, smb + 4u * (uint32_t)(2 * G1_AW + s * G1_BW + n * AST + kw));
            b1f[np * 2][0] = q[0]; b1f[np * 2 + 1][0] = q[1];
            b1f[np * 2][1] = q[2]; b1f[np * 2 + 1][1] = q[3];
            ldmx4(q, smb + 4u * (uint32_t)(2 * G1_AW + 2 * G1_BW + s * G1_BW + n * AST + kw));
            b3f[np * 2][0] = q[0]; b3f[np * 2 + 1][0] = q[1];
            b3f[np * 2][1] = q[2]; b3f[np * 2 + 1][1] = q[3];
        }
        #pragma unroll
        for (int ni = 0; ni < 4; ++ni)
            #pragma unroll
            for (int mi = 0; mi < 2; ++mi) {
                mma_f16(accG[mi][ni], af[mi], b1f[ni]);
                mma_f16(accU[mi][ni], af[mi], b3f[ni]);
            }
    };

    const int KT = dH / TBK;   // 16
    cpaA(0, 0); cpa_commit();
    ldgB(0, 0); stsB(0, 0);
    ldgB(0, 1); stsB(0, 1);
    cpa_wait0();
    __syncthreads();

    for (int kt = 0; kt < KT; ++kt) {
        const int s = kt & 1;
        const bool more = (kt + 1 < KT);
        if (more) { cpaA(kt + 1, s ^ 1); cpa_commit(); ldgB(kt + 1, 0); }

        compute_ks(s, 0);
        compute_ks(s, 1);

        if (more) { stsB(s ^ 1, 0); ldgB(kt + 1, 1); }

        compute_ks(s, 2);
        compute_ks(s, 3);

        if (more) stsB(s ^ 1, 1);
        cpa_wait0();
        __syncthreads();
    }

    #pragma unroll
    for (int mi = 0; mi < 2; ++mi) {
        int r0 = m0 + wm * 32 + mi * 16 + lr;
        int r1 = r0 + 8;
        #pragma unroll
        for (int ni = 0; ni < 4; ++ni) {
            int c = i0 + wn * 32 + ni * 8 + lc * 2;
            if (r0 < mEnd) {
                float g0 = accG[mi][ni][0], g1 = accG[mi][ni][1];
                float u0 = accU[mi][ni][0], u1 = accU[mi][ni][1];
                float h0 = g0 / (1.0f + __expf(-g0)) * u0;
                float h1 = g1 / (1.0f + __expf(-g1)) * u1;
                *(uint32_t*)&g_h[(size_t)r0 * dI + c] = packh2(h0, h1);
            }
            if (r1 < mEnd) {
                float g2 = accG[mi][ni][2], g3 = accG[mi][ni][3];
                float u2 = accU[mi][ni][2], u3 = accU[mi][ni][3];
                float h2 = g2 / (1.0f + __expf(-g2)) * u2;
                float h3 = g3 / (1.0f + __expf(-g3)) * u3;
                *(uint32_t*)&g_h[(size_t)r1 * dI + c] = packh2(h2, h3);
            }
        }
    }
}

// ============ GEMM2: CTA 128x128, warp 32x64, k64, A via cp.async — out += ew*(h@w2) ============
__global__ void __launch_bounds__(NTH, 2)
gemm2_mma(const float* __restrict__ ew,
          const float* __restrict__ w2,
          float* __restrict__ out) {
    const int e    = blockIdx.z;
    const int mEnd = g_off[e + 1];
    const int m0   = g_off[e] + blockIdx.x * G2_TBM;
    if (m0 >= mEnd) return;
    const int h0 = blockIdx.y * G2_TBN;

    extern __shared__ uint32_t dsm[];

    const int t = threadIdx.x;
    const int w = t >> 5, l = t & 31;
    const int wm = w & 3, wn = w >> 2;      // warp tile 32x64
    const int lr = l >> 2, lc = l & 3;
    const uint32_t smb = su32(dsm);
    const int lmRow = l & 15;
    const int lmChk = (l >> 4) * 4;

    const float* w2e = w2 + (size_t)e * dI * dH + h0;

    uint32_t aDstW[4];
    const __half* aSrc[4];
    #pragma unroll
    for (int p = 0; p < 4; ++p) {
        int id = t + p * NTH;
        int row = id >> 3, qc = id & 7;
        aDstW[p] = (uint32_t)(row * AST + qc * 4);
        int grow = (m0 + row < mEnd) ? (m0 + row) : m0;
        aSrc[p] = g_h + (size_t)grow * dI + qc * 8;
    }
    const int bN = t & 127, bKb = (t >> 7) * 16;
    const int bOffW = bN * AST + (bKb >> 1);
    const float* bSrc = w2e + (size_t)bKb * dH + bN;

    uint32_t uB[8];

    auto cpaA = [&](int kt, int s) {
        const int k0 = kt * TBK;
        #pragma unroll
        for (int p = 0; p < 4; ++p)
            cpa16(smb + 4u * (s * G2_AW + aDstW[p]), aSrc[p] + k0);
    };
    auto ldgB = [&](int kt, int h) {
        const float* pb = bSrc + (size_t)(kt * TBK + h * 32) * dH;
        #pragma unroll
        for (int jj = 0; jj < 8; ++jj)
            uB[jj] = packh2(pb[(size_t)(2 * jj) * dH], pb[(size_t)(2 * jj + 1) * dH]);
    };
    auto stsB = [&](int s, int h) {
        *(uint4*)&dsm[2 * G2_AW + s * G2_BW + bOffW + h * 16] =
            make_uint4(uB[0], uB[1], uB[2], uB[3]);
        *(uint4*)&dsm[2 * G2_AW + s * G2_BW + bOffW + h * 16 + 4] =
            make_uint4(uB[4], uB[5], uB[6], uB[7]);
    };

    float acc[2][8][4] = {};

    auto compute_ks = [&](int s, int ks) {
        const int kw = ks * 8 + lmChk;
        uint32_t af[2][4];
        #pragma unroll
        for (int mi = 0; mi < 2; ++mi) {
            int r = wm * 32 + mi * 16 + lmRow;
            ldmx4(af[mi], smb + 4u * (uint32_t)(s * G2_AW + r * AST + kw));
        }
        uint32_t bf[8][2];
        #pragma unroll
        for (int np = 0; np < 4; ++np) {
            int n = wn * 64 + np * 16 + lmRow;
            uint32_t q[4];
            ldmx4(q, smb + 4u * (uint32_t)(2 * G2_AW + s * G2_BW + n * AST + kw));
            bf[np * 2][0] = q[0]; bf[np * 2 + 1][0] = q[1];
            bf[np * 2][1] = q[2]; bf[np * 2 + 1][1] = q[3];
        }
        #pragma unroll
        for (int ni = 0; ni < 8; ++ni)
            #pragma unroll
            for (int mi = 0; mi < 2; ++mi)
                mma_f16(acc[mi][ni], af[mi], bf[ni]);
    };

    const int KT = dI / TBK;   // 64
    cpaA(0, 0); cpa_commit();
    ldgB(0, 0); stsB(0, 0);
    ldgB(0, 1); stsB(0, 1);
    cpa_wait0();
    __syncthreads();

    for (int kt = 0; kt < KT; ++kt) {
        const int s = kt & 1;
        const bool more = (kt + 1 < KT);
        if (more) { cpaA(kt + 1, s ^ 1); cpa_commit(); ldgB(kt + 1, 0); }

        compute_ks(s, 0);
        compute_ks(s, 1);

        if (more) { stsB(s ^ 1, 0); ldgB(kt + 1, 1); }

        compute_ks(s, 2);
        compute_ks(s, 3);

        if (more) stsB(s ^ 1, 1);
        cpa_wait0();
        __syncthreads();
    }

    // fused epilogue: out[token] += ew * acc (exactly 2 adds per element)
    #pragma unroll
    for (int mi = 0; mi < 2; ++mi) {
        int r0 = m0 + wm * 32 + mi * 16 + lr;
        int r1 = r0 + 8;
        int tk0 = -1, tk1 = -1;
        float wg0 = 0.0f, wg1 = 0.0f;
        if (r0 < mEnd) { int p = g_pairs[r0]; wg0 = ew[p]; tk0 = p / dK; }
        if (r1 < mEnd) { int p = g_pairs[r1]; wg1 = ew[p]; tk1 = p / dK; }
        #pragma unroll
        for (int ni = 0; ni < 8; ++ni) {
            int c = h0 + wn * 64 + ni * 8 + lc * 2;
            if (tk0 >= 0) {
                atomicAdd(&out[(size_t)tk0 * dH + c],     wg0 * acc[mi][ni][0]);
                atomicAdd(&out[(size_t)tk0 * dH + c + 1], wg0 * acc[mi][ni][1]);
            }
            if (tk1 >= 0) {
                atomicAdd(&out[(size_t)tk1 * dH + c],     wg1 * acc[mi][ni][2]);
                atomicAdd(&out[(size_t)tk1 * dH + c + 1], wg1 * acc[mi][ni][3]);
            }
        }
    }
}

extern "C" void kernel_launch(void* const* d_in, const int* in_sizes, int n_in,
                              void* d_out, int out_size) {
    const float* x   = (const float*)d_in[0];
    const int*   idx = (const int*)  d_in[1];
    const float* ew  = (const float*)d_in[2];
    const float* w1  = (const float*)d_in[3];
    const float* w2  = (const float*)d_in[4];
    const float* w3  = (const float*)d_in[5];
    float* out = (float*)d_out;

    const int smem1 = G1_SMEM_W * 4;   // 73728 B
    const int smem2 = G2_SMEM_W * 4;   // 73728 B
    cudaFuncSetAttribute(gemm1_mma, cudaFuncAttributeMaxDynamicSharedMemorySize, smem1);
    cudaFuncSetAttribute(gemm2_mma, cudaFuncAttributeMaxDynamicSharedMemorySize, smem2);

    route_kernel<<<1, 256>>>(idx);
    cvt_x_kernel<<<(dN * dH / 4 + 255) / 256, 256>>>(x);
    zero_out_kernel<<<(dN * dH / 4 + 255) / 256, 256>>>(out);
    dim3 g1(dNK / G1_TBM, dI / G1_TBN, dE);   // 32 x 64 x 8
    gemm1_mma<<<g1, NTH, smem1>>>(w1, w3);
    dim3 g2(dNK / G2_TBM, dH / G2_TBN, dE);   // 32 x 8 x 8
    gemm2_mma<<<g2, NTH, smem2>>>(ew, w2, out);
}

// round 15
// speedup vs baseline: 1.6157x; 1.0013x over previous
#include <cuda_runtime.h>
#include <cuda_fp16.h>
#include <cstdint>

#define dE 8
#define dH 1024
#define dI 4096
#define dN 2048
#define dK 2
#define dNK 4096

#define TBK 64
#define NTH 256
#define MAXTILES 40

// smem: row stride 36 words (144B) — 16B-aligned rows for ldmatrix; conflict-free
#define AST 36

// ---- GEMM1 geometry: CTA 128x64, warp tile 32x32 (dual-matrix) ----
#define G1_TBM 128
#define G1_TBN 64
#define G1_AW (G1_TBM * AST)
#define G1_BW (G1_TBN * AST)
#define G1_SMEM_W (2 * G1_AW + 4 * G1_BW)   // 72 KB

// ---- GEMM2 geometry: CTA 128x128, warp tile 32x64 ----
#define G2_TBM 128
#define G2_TBN 128
#define G2_AW (G2_TBM * AST)
#define G2_BW (G2_TBN * AST)
#define G2_SMEM_W (2 * G2_AW + 2 * G2_BW)   // 72 KB

// ---- scratch (device globals; no runtime allocation) ----
__device__ int    g_pairs[dNK];
__device__ int    g_off[dE + 1];
__device__ int2   g_tiles[MAXTILES];
__device__ int    g_ntiles;
__device__ __half g_x[(size_t)dN * dH];    // x in fp16 (4 MB, L2-resident)
__device__ __half g_h[(size_t)dNK * dI];   // SwiGLU hidden, fp16 (32 MB)

__device__ __forceinline__ uint32_t su32(const void* p) {
    return (uint32_t)__cvta_generic_to_shared(p);
}
__device__ __forceinline__ uint32_t packh2(float lo, float hi) {
    __half2 h = __floats2half2_rn(lo, hi);
    return *(uint32_t*)&h;
}
__device__ __forceinline__ void mma_f16(float* d, const uint32_t* a, const uint32_t* b) {
    asm volatile("mma.sync.aligned.m16n8k16.row.col.f32.f16.f16.f32 "
                 "{%0,%1,%2,%3}, {%4,%5,%6,%7}, {%8,%9}, {%0,%1,%2,%3};\n"
                 : "+f"(d[0]), "+f"(d[1]), "+f"(d[2]), "+f"(d[3])
                 : "r"(a[0]), "r"(a[1]), "r"(a[2]), "r"(a[3]),
                   "r"(b[0]), "r"(b[1]));
}
__device__ __forceinline__ void ldmx4(uint32_t* r, uint32_t addr) {
    asm volatile("ldmatrix.sync.aligned.m8n8.x4.shared.b16 {%0,%1,%2,%3}, [%4];"
                 : "=r"(r[0]), "=r"(r[1]), "=r"(r[2]), "=r"(r[3]) : "r"(addr));
}
__device__ __forceinline__ void cpa16(uint32_t dst, const void* src) {
    asm volatile("cp.async.cg.shared.global [%0], [%1], 16;\n" :: "r"(dst), "l"(src));
}
__device__ __forceinline__ void cpa_commit() { asm volatile("cp.async.commit_group;\n"); }
__device__ __forceinline__ void cpa_wait0()  { asm volatile("cp.async.wait_group 0;\n"); }

// ---- routing: histogram + scan + scatter + tile table, single CTA ----
__global__ void route_kernel(const int* __restrict__ idx) {
    __shared__ int s_cnt[dE], s_base[dE];
    int t = threadIdx.x;
    if (t < dE) s_cnt[t] = 0;
    __syncthreads();
    for (int p = t; p < dNK; p += blockDim.x) atomicAdd(&s_cnt[idx[p]], 1);
    __syncthreads();
    if (t == 0) {
        int acc = 0;
        for (int e = 0; e < dE; ++e) { g_off[e] = acc; s_base[e] = acc; acc += s_cnt[e]; }
        g_off[dE] = acc;
        int nt = 0;
        for (int e = 0; e < dE; ++e)
            for (int m = g_off[e]; m < g_off[e + 1]; m += G1_TBM)
                g_tiles[nt++] = make_int2(e, m);
        g_ntiles = nt;
    }
    __syncthreads();
    if (t < dE) s_cnt[t] = 0;
    __syncthreads();
    for (int p = t; p < dNK; p += blockDim.x) {
        int e = idx[p];
        int slot = s_base[e] + atomicAdd(&s_cnt[e], 1);
        g_pairs[slot] = p;
    }
}

// ---- zero out + convert x -> fp16 ----
__global__ void zero_out_kernel(float* __restrict__ out) {
    int i = blockIdx.x * blockDim.x + threadIdx.x;
    if (i < dN * dH / 4) ((float4*)out)[i] = make_float4(0.f, 0.f, 0.f, 0.f);
}
__global__ void cvt_x_kernel(const float* __restrict__ x) {
    int i = blockIdx.x * blockDim.x + threadIdx.x;
    if (i >= dN * dH / 4) return;
    float4 v = ((const float4*)x)[i];
    uint2 o = make_uint2(packh2(v.x, v.y), packh2(v.z, v.w));
    *(uint2*)&g_x[(size_t)i * 4] = o;
}

// ============ GEMM1: CTA 128x64, warp 32x32 dual, k64, A via cp.async ============
__global__ void __launch_bounds__(NTH, 2)
gemm1_mma(const float* __restrict__ w1,
          const float* __restrict__ w3) {
    if ((int)blockIdx.x >= g_ntiles) return;
    const int2 tile = g_tiles[blockIdx.x];
    const int e    = tile.x;
    const int m0   = tile.y;
    const int mEnd = g_off[e + 1];
    const int i0   = blockIdx.y * G1_TBN;

    extern __shared__ uint32_t dsm[];
    __shared__ int s_tok[G1_TBM];

    const int t = threadIdx.x;
    const int w = t >> 5, l = t & 31;
    const int wm = w & 3, wn = w >> 2;
    const int lr = l >> 2, lc = l & 3;
    const uint32_t smb = su32(dsm);
    const int lmRow = l & 15;
    const int lmChk = (l >> 4) * 4;

    if (t < G1_TBM) { int s = m0 + t; s_tok[t] = (s < mEnd) ? g_pairs[s] / dK : -1; }
    __syncthreads();

    const float* w1e = w1 + (size_t)e * dH * dI + i0;
    const float* w3e = w3 + (size_t)e * dH * dI + i0;

    // A staging via cp.async: 128 rows x 128B per stage -> 4x16B per thread
    uint32_t aDstW[4];
    const __half* aSrc[4];
    #pragma unroll
    for (int p = 0; p < 4; ++p) {
        int id = t + p * NTH;
        int row = id >> 3, ch = id & 7;
        aDstW[p] = (uint32_t)(row * AST + ch * 4);
        int tok = s_tok[row];
        aSrc[p] = g_x + (size_t)(tok < 0 ? 0 : tok) * dH + ch * 8;
    }
    const int bN = t & 63, bKb = (t >> 6) * 8;
    const int bOffW = bN * AST + (bKb >> 1);
    const float* b1Src = w1e + (size_t)bKb * dI + bN;
    const float* b3Src = w3e + (size_t)bKb * dI + bN;

    uint32_t uB1[4], uB3[4];

    auto cpaA = [&](int kt, int s) {
        const int k0 = kt * TBK;
        #pragma unroll
        for (int p = 0; p < 4; ++p)
            cpa16(smb + 4u * (s * G1_AW + aDstW[p]), aSrc[p] + k0);
    };
    auto ldgB = [&](int kt, int h) {
        const float* pb1 = b1Src + (size_t)(kt * TBK + h * 32) * dI;
        const float* pb3 = b3Src + (size_t)(kt * TBK + h * 32) * dI;
        #pragma unroll
        for (int jj = 0; jj < 4; ++jj) {
            uB1[jj] = packh2(pb1[(size_t)(2 * jj) * dI], pb1[(size_t)(2 * jj + 1) * dI]);
            uB3[jj] = packh2(pb3[(size_t)(2 * jj) * dI], pb3[(size_t)(2 * jj + 1) * dI]);
        }
    };
    auto stsB = [&](int s, int h) {
        *(uint4*)&dsm[2 * G1_AW + s * G1_BW + bOffW + h * 16] =
            make_uint4(uB1[0], uB1[1], uB1[2], uB1[3]);
        *(uint4*)&dsm[2 * G1_AW + 2 * G1_BW + s * G1_BW + bOffW + h * 16] =
            make_uint4(uB3[0], uB3[1], uB3[2], uB3[3]);
    };

    // hoisted ldmatrix byte-address bases (s=0, kw=0)
    uint32_t aBase[2], b1Base[2], b3Base[2];
    #pragma unroll
    for (int mi = 0; mi < 2; ++mi)
        aBase[mi] = smb + 4u * (uint32_t)((wm * 32 + mi * 16 + lmRow) * AST);
    #pragma unroll
    for (int np = 0; np < 2; ++np) {
        int n = wn * 32 + np * 16 + lmRow;
        b1Base[np] = smb + 4u * (uint32_t)(2 * G1_AW + n * AST);
        b3Base[np] = smb + 4u * (uint32_t)(2 * G1_AW + 2 * G1_BW + n * AST);
    }

    float accG[2][4][4] = {};
    float accU[2][4][4] = {};

    auto compute_ks = [&](int s, int ks) {
        const uint32_t aOff = (uint32_t)(s * 4 * G1_AW) + 4u * (uint32_t)(ks * 8 + lmChk);
        const uint32_t bOff = (uint32_t)(s * 4 * G1_BW) + 4u * (uint32_t)(ks * 8 + lmChk);
        uint32_t af[2][4];
        #pragma unroll
        for (int mi = 0; mi < 2; ++mi)
            ldmx4(af[mi], aBase[mi] + aOff);
        uint32_t b1f[4][2], b3f[4][2];
        #pragma unroll
        for (int np = 0; np < 2; ++np) {
            uint32_t q[4];
            ldmx4(q, b1Base[np] + bOff);
            b1f[np * 2][0] = q[0]; b1f[np * 2 + 1][0] = q[1];
            b1f[np * 2][1] = q[2]; b1f[np * 2 + 1][1] = q[3];
            ldmx4(q, b3Base[np] + bOff);
            b3f[np * 2][0] = q[0]; b3f[np * 2 + 1][0] = q[1];
            b3f[np * 2][1] = q[2]; b3f[np * 2 + 1][1] = q[3];
        }
        #pragma unroll
        for (int ni = 0; ni < 4; ++ni)
            #pragma unroll
            for (int mi = 0; mi < 2; ++mi) {
                mma_f16(accG[mi][ni], af[mi], b1f[ni]);
                mma_f16(accU[mi][ni], af[mi], b3f[ni]);
            }
    };

    const int KT = dH / TBK;   // 16
    cpaA(0, 0); cpa_commit();
    ldgB(0, 0); stsB(0, 0);
    ldgB(0, 1); stsB(0, 1);
    cpa_wait0();
    __syncthreads();

    for (int kt = 0; kt < KT; ++kt) {
        const int s = kt & 1;
        const bool more = (kt + 1 < KT);
        if (more) { cpaA(kt + 1, s ^ 1); cpa_commit(); ldgB(kt + 1, 0); }

        compute_ks(s, 0);
        compute_ks(s, 1);

        if (more) { stsB(s ^ 1, 0); ldgB(kt + 1, 1); }

        compute_ks(s, 2);
        compute_ks(s, 3);

        if (more) {
            stsB(s ^ 1, 1);
            cpa_wait0();
            __syncthreads();
        }
    }

    #pragma unroll
    for (int mi = 0; mi < 2; ++mi) {
        int r0 = m0 + wm * 32 + mi * 16 + lr;
        int r1 = r0 + 8;
        #pragma unroll
        for (int ni = 0; ni < 4; ++ni) {
            int c = i0 + wn * 32 + ni * 8 + lc * 2;
            if (r0 < mEnd) {
                float g0 = accG[mi][ni][0], g1 = accG[mi][ni][1];
                float u0 = accU[mi][ni][0], u1 = accU[mi][ni][1];
                float h0 = g0 / (1.0f + __expf(-g0)) * u0;
                float h1 = g1 / (1.0f + __expf(-g1)) * u1;
                *(uint32_t*)&g_h[(size_t)r0 * dI + c] = packh2(h0, h1);
            }
            if (r1 < mEnd) {
                float g2 = accG[mi][ni][2], g3 = accG[mi][ni][3];
                float u2 = accU[mi][ni][2], u3 = accU[mi][ni][3];
                float h2 = g2 / (1.0f + __expf(-g2)) * u2;
                float h3 = g3 / (1.0f + __expf(-g3)) * u3;
                *(uint32_t*)&g_h[(size_t)r1 * dI + c] = packh2(h2, h3);
            }
        }
    }
}

// ============ GEMM2: CTA 128x128, warp 32x64, k64, A via cp.async — out += ew*(h@w2) ============
__global__ void __launch_bounds__(NTH, 2)
gemm2_mma(const float* __restrict__ ew,
          const float* __restrict__ w2,
          float* __restrict__ out) {
    if ((int)blockIdx.x >= g_ntiles) return;
    const int2 tile = g_tiles[blockIdx.x];
    const int e    = tile.x;
    const int m0   = tile.y;
    const int mEnd = g_off[e + 1];
    const int h0   = blockIdx.y * G2_TBN;

    extern __shared__ uint32_t dsm[];

    const int t = threadIdx.x;
    const int w = t >> 5, l = t & 31;
    const int wm = w & 3, wn = w >> 2;      // warp tile 32x64
    const int lr = l >> 2, lc = l & 3;
    const uint32_t smb = su32(dsm);
    const int lmRow = l & 15;
    const int lmChk = (l >> 4) * 4;

    const float* w2e = w2 + (size_t)e * dI * dH + h0;

    uint32_t aDstW[4];
    const __half* aSrc[4];
    #pragma unroll
    for (int p = 0; p < 4; ++p) {
        int id = t + p * NTH;
        int row = id >> 3, qc = id & 7;
        aDstW[p] = (uint32_t)(row * AST + qc * 4);
        int grow = (m0 + row < mEnd) ? (m0 + row) : m0;
        aSrc[p] = g_h + (size_t)grow * dI + qc * 8;
    }
    const int bN = t & 127, bKb = (t >> 7) * 16;
    const int bOffW = bN * AST + (bKb >> 1);
    const float* bSrc = w2e + (size_t)bKb * dH + bN;

    uint32_t uB[8];

    auto cpaA = [&](int kt, int s) {
        const int k0 = kt * TBK;
        #pragma unroll
        for (int p = 0; p < 4; ++p)
            cpa16(smb + 4u * (s * G2_AW + aDstW[p]), aSrc[p] + k0);
    };
    auto ldgB = [&](int kt, int h) {
        const float* pb = bSrc + (size_t)(kt * TBK + h * 32) * dH;
        #pragma unroll
        for (int jj = 0; jj < 8; ++jj)
            uB[jj] = packh2(pb[(size_t)(2 * jj) * dH], pb[(size_t)(2 * jj + 1) * dH]);
    };
    auto stsB = [&](int s, int h) {
        *(uint4*)&dsm[2 * G2_AW + s * G2_BW + bOffW + h * 16] =
            make_uint4(uB[0], uB[1], uB[2], uB[3]);
        *(uint4*)&dsm[2 * G2_AW + s * G2_BW + bOffW + h * 16 + 4] =
            make_uint4(uB[4], uB[5], uB[6], uB[7]);
    };

    // hoisted ldmatrix bases
    uint32_t aBase[2], bBase[4];
    #pragma unroll
    for (int mi = 0; mi < 2; ++mi)
        aBase[mi] = smb + 4u * (uint32_t)((wm * 32 + mi * 16 + lmRow) * AST);
    #pragma unroll
    for (int np = 0; np < 4; ++np) {
        int n = wn * 64 + np * 16 + lmRow;
        bBase[np] = smb + 4u * (uint32_t)(2 * G2_AW + n * AST);
    }

    float acc[2][8][4] = {};

    auto compute_ks = [&](int s, int ks) {
        const uint32_t aOff = (uint32_t)(s * 4 * G2_AW) + 4u * (uint32_t)(ks * 8 + lmChk);
        const uint32_t bOff = (uint32_t)(s * 4 * G2_BW) + 4u * (uint32_t)(ks * 8 + lmChk);
        uint32_t af[2][4];
        #pragma unroll
        for (int mi = 0; mi < 2; ++mi)
            ldmx4(af[mi], aBase[mi] + aOff);
        uint32_t bf[8][2];
        #pragma unroll
        for (int np = 0; np < 4; ++np) {
            uint32_t q[4];
            ldmx4(q, bBase[np] + bOff);
            bf[np * 2][0] = q[0]; bf[np * 2 + 1][0] = q[1];
            bf[np * 2][1] = q[2]; bf[np * 2 + 1][1] = q[3];
        }
        #pragma unroll
        for (int ni = 0; ni < 8; ++ni)
            #pragma unroll
            for (int mi = 0; mi < 2; ++mi)
                mma_f16(acc[mi][ni], af[mi], bf[ni]);
    };

    const int KT = dI / TBK;   // 64
    cpaA(0, 0); cpa_commit();
    ldgB(0, 0); stsB(0, 0);
    ldgB(0, 1); stsB(0, 1);
    cpa_wait0();
    __syncthreads();

    for (int kt = 0; kt < KT; ++kt) {
        const int s = kt & 1;
        const bool more = (kt + 1 < KT);
        if (more) { cpaA(kt + 1, s ^ 1); cpa_commit(); ldgB(kt + 1, 0); }

        compute_ks(s, 0);
        compute_ks(s, 1);

        if (more) { stsB(s ^ 1, 0); ldgB(kt + 1, 1); }

        compute_ks(s, 2);
        compute_ks(s, 3);

        if (more) {
            stsB(s ^ 1, 1);
            cpa_wait0();
            __syncthreads();
        }
    }

    // fused epilogue: out[token] += ew * acc (exactly 2 adds per element)
    #pragma unroll
    for (int mi = 0; mi < 2; ++mi) {
        int r0 = m0 + wm * 32 + mi * 16 + lr;
        int r1 = r0 + 8;
        int tk0 = -1, tk1 = -1;
        float wg0 = 0.0f, wg1 = 0.0f;
        if (r0 < mEnd) { int p = g_pairs[r0]; wg0 = ew[p]; tk0 = p / dK; }
        if (r1 < mEnd) { int p = g_pairs[r1]; wg1 = ew[p]; tk1 = p / dK; }
        #pragma unroll
        for (int ni = 0; ni < 8; ++ni) {
            int c = h0 + wn * 64 + ni * 8 + lc * 2;
            if (tk0 >= 0) {
                atomicAdd(&out[(size_t)tk0 * dH + c],     wg0 * acc[mi][ni][0]);
                atomicAdd(&out[(size_t)tk0 * dH + c + 1], wg0 * acc[mi][ni][1]);
            }
            if (tk1 >= 0) {
                atomicAdd(&out[(size_t)tk1 * dH + c],     wg1 * acc[mi][ni][2]);
                atomicAdd(&out[(size_t)tk1 * dH + c + 1], wg1 * acc[mi][ni][3]);
            }
        }
    }
}

extern "C" void kernel_launch(void* const* d_in, const int* in_sizes, int n_in,
                              void* d_out, int out_size) {
    const float* x   = (const float*)d_in[0];
    const int*   idx = (const int*)  d_in[1];
    const float* ew  = (const float*)d_in[2];
    const float* w1  = (const float*)d_in[3];
    const float* w2  = (const float*)d_in[4];
    const float* w3  = (const float*)d_in[5];
    float* out = (float*)d_out;

    const int smem1 = G1_SMEM_W * 4;   // 73728 B
    const int smem2 = G2_SMEM_W * 4;   // 73728 B
    cudaFuncSetAttribute(gemm1_mma, cudaFuncAttributeMaxDynamicSharedMemorySize, smem1);
    cudaFuncSetAttribute(gemm2_mma, cudaFuncAttributeMaxDynamicSharedMemorySize, smem2);

    route_kernel<<<1, 256>>>(idx);
    cvt_x_kernel<<<(dN * dH / 4 + 255) / 256, 256>>>(x);
    zero_out_kernel<<<(dN * dH / 4 + 255) / 256, 256>>>(out);
    dim3 g1(MAXTILES, dI / G1_TBN, 1);   // 40 x 64, nearly all tiles real
    gemm1_mma<<<g1, NTH, smem1>>>(w1, w3);
    dim3 g2(MAXTILES, dH / G2_TBN, 1);   // 40 x 8
    gemm2_mma<<<g2, NTH, smem2>>>(ew, w2, out);
}

// round 17
// speedup vs baseline: 1.7185x; 1.0636x over previous
#include <cuda_runtime.h>
#include <cuda_fp16.h>
#include <cstdint>

#define dE 8
#define dH 1024
#define dI 4096
#define dN 2048
#define dK 2
#define dNK 4096

#define TBK 64
#define NTH 256
#define MAXTILES 40

// swizzled smem: rows are exactly 128B (32 words); 16B chunk c of row r lives at
// chunk (c ^ (r & 7)) — conflict-free for cp.async, STS.128 and ldmatrix.

// ---- GEMM1: CTA 128x64, warp 32x32 dual ----
#define G1_A_ST 4096
#define G1_B_ST 2048
#define G1_B1W  12288
#define G1_B3W  18432
#define G1_SMEM_W 24576    // 96 KB

// ---- GEMM2: CTA 128x128, warp 32x64 ----
#define G2_A_ST 4096
#define G2_B_ST 4096
#define G2_BW   12288
#define G2_SMEM_W 24576    // 96 KB

// ---- scratch (device globals; no runtime allocation) ----
__device__ int    g_pairs[dNK];
__device__ int    g_off[dE + 1];
__device__ int2   g_tiles[MAXTILES];
__device__ int    g_ntiles;
__device__ __half g_x[(size_t)dN * dH];
__device__ __half g_h[(size_t)dNK * dI];

__device__ __forceinline__ uint32_t su32(const void* p) {
    return (uint32_t)__cvta_generic_to_shared(p);
}
__device__ __forceinline__ uint32_t packh2(float lo, float hi) {
    __half2 h = __floats2half2_rn(lo, hi);
    return *(uint32_t*)&h;
}
__device__ __forceinline__ void mma_f16(float* d, const uint32_t* a, const uint32_t* b) {
    asm volatile("mma.sync.aligned.m16n8k16.row.col.f32.f16.f16.f32 "
                 "{%0,%1,%2,%3}, {%4,%5,%6,%7}, {%8,%9}, {%0,%1,%2,%3};\n"
                 : "+f"(d[0]), "+f"(d[1]), "+f"(d[2]), "+f"(d[3])
                 : "r"(a[0]), "r"(a[1]), "r"(a[2]), "r"(a[3]),
                   "r"(b[0]), "r"(b[1]));
}
__device__ __forceinline__ void ldmx4(uint32_t* r, uint32_t addr) {
    asm volatile("ldmatrix.sync.aligned.m8n8.x4.shared.b16 {%0,%1,%2,%3}, [%4];"
                 : "=r"(r[0]), "=r"(r[1]), "=r"(r[2]), "=r"(r[3]) : "r"(addr));
}
__device__ __forceinline__ void cpa16(uint32_t dst, const void* src) {
    asm volatile("cp.async.cg.shared.global [%0], [%1], 16;\n" :: "r"(dst), "l"(src));
}
__device__ __forceinline__ void cpa_commit() { asm volatile("cp.async.commit_group;\n"); }
__device__ __forceinline__ void cpa_wait0()  { asm volatile("cp.async.wait_group 0;\n"); }
__device__ __forceinline__ void cpa_wait1()  { asm volatile("cp.async.wait_group 1;\n"); }

// ---- routing: histogram + scan + scatter + tile table, single CTA ----
__global__ void route_kernel(const int* __restrict__ idx) {
    __shared__ int s_cnt[dE], s_base[dE];
    int t = threadIdx.x;
    if (t < dE) s_cnt[t] = 0;
    __syncthreads();
    for (int p = t; p < dNK; p += blockDim.x) atomicAdd(&s_cnt[idx[p]], 1);
    __syncthreads();
    if (t == 0) {
        int acc = 0;
        for (int e = 0; e < dE; ++e) { g_off[e] = acc; s_base[e] = acc; acc += s_cnt[e]; }
        g_off[dE] = acc;
        int nt = 0;
        for (int e = 0; e < dE; ++e)
            for (int m = g_off[e]; m < g_off[e + 1]; m += 128)
                g_tiles[nt++] = make_int2(e, m);
        g_ntiles = nt;
    }
    __syncthreads();
    if (t < dE) s_cnt[t] = 0;
    __syncthreads();
    for (int p = t; p < dNK; p += blockDim.x) {
        int e = idx[p];
        int slot = s_base[e] + atomicAdd(&s_cnt[e], 1);
        g_pairs[slot] = p;
    }
}

__global__ void zero_out_kernel(float* __restrict__ out) {
    int i = blockIdx.x * blockDim.x + threadIdx.x;
    if (i < dN * dH / 4) ((float4*)out)[i] = make_float4(0.f, 0.f, 0.f, 0.f);
}
__global__ void cvt_x_kernel(const float* __restrict__ x) {
    int i = blockIdx.x * blockDim.x + threadIdx.x;
    if (i >= dN * dH / 4) return;
    float4 v = ((const float4*)x)[i];
    uint2 o = make_uint2(packh2(v.x, v.y), packh2(v.z, v.w));
    *(uint2*)&g_x[(size_t)i * 4] = o;
}

// ============ GEMM1: CTA 128x64, warp 32x32 dual, 3-stage ============
__global__ void __launch_bounds__(NTH, 2)
gemm1_mma(const float* __restrict__ w1,
          const float* __restrict__ w3) {
    if ((int)blockIdx.x >= g_ntiles) return;
    const int2 tile = g_tiles[blockIdx.x];
    const int e    = tile.x;
    const int m0   = tile.y;
    const int mEnd = g_off[e + 1];
    const int i0   = blockIdx.y * 64;

    extern __shared__ uint32_t dsm[];
    __shared__ int s_tok[128];

    const int t = threadIdx.x;
    const int w = t >> 5, l = t & 31;
    const int wm = w & 3, wn = w >> 2;
    const int lr = l >> 2, lc = l & 3;
    const uint32_t smb = su32(dsm);
    const int lmRow = l & 15;
    const int rx7   = lmRow & 7;
    const int hi    = l >> 4;            // 0 or 1: which 16B chunk within the k16 step

    if (t < 128) { int s = m0 + t; s_tok[t] = (s < mEnd) ? g_pairs[s] / dK : -1; }
    __syncthreads();

    const float* w1e = w1 + (size_t)e * dH * dI + i0;
    const float* w3e = w3 + (size_t)e * dH * dI + i0;

    // A via cp.async: 4 x 16B per thread; dst chunk swizzled
    uint32_t aDstW[4];
    const __half* aSrc[4];
    #pragma unroll
    for (int p = 0; p < 4; ++p) {
        int id = t + p * NTH;
        int row = id >> 3, ch = id & 7;
        aDstW[p] = (uint32_t)(row * 32 + ((ch ^ (row & 7)) * 4));
        int tok = s_tok[row];
        aSrc[p] = g_x + (size_t)(tok < 0 ? 0 : tok) * dH + ch * 8;
    }
    const int bN = t & 63, cIdx = t >> 6;   // cIdx 0..3
    const int bKb = cIdx * 8;
    const float* b1Src = w1e + (size_t)bKb * dI + bN;
    const float* b3Src = w3e + (size_t)bKb * dI + bN;

    uint32_t uB1[4], uB3[4];

    auto cpaA = [&](int kt, int s) {
        const int k0 = kt * TBK;
        #pragma unroll
        for (int p = 0; p < 4; ++p)
            cpa16(smb + 4u * (s * G1_A_ST + aDstW[p]), aSrc[p] + k0);
    };
    auto ldgB = [&](int kt, int h) {
        const float* pb1 = b1Src + (size_t)(kt * TBK + h * 32) * dI;
        const float* pb3 = b3Src + (size_t)(kt * TBK + h * 32) * dI;
        #pragma unroll
        for (int jj = 0; jj < 4; ++jj) {
            uB1[jj] = packh2(pb1[(size_t)(2 * jj) * dI], pb1[(size_t)(2 * jj + 1) * dI]);
            uB3[jj] = packh2(pb3[(size_t)(2 * jj) * dI], pb3[(size_t)(2 * jj + 1) * dI]);
        }
    };
    auto stsB = [&](int s, int h) {
        int chunk = 4 * h + cIdx;
        int off = bN * 32 + ((chunk ^ (bN & 7)) * 4);
        *(uint4*)&dsm[G1_B1W + s * G1_B_ST + off] = make_uint4(uB1[0], uB1[1], uB1[2], uB1[3]);
        *(uint4*)&dsm[G1_B3W + s * G1_B_ST + off] = make_uint4(uB3[0], uB3[1], uB3[2], uB3[3]);
    };

    // ldmatrix per-thread row base addresses (no chunk offset)
    uint32_t aBase[2], b1Base[2], b3Base[2];
    #pragma unroll
    for (int mi = 0; mi < 2; ++mi)
        aBase[mi] = smb + (uint32_t)((wm * 32 + mi * 16 + lmRow) * 128);
    #pragma unroll
    for (int np = 0; np < 2; ++np) {
        int n = wn * 32 + np * 16 + lmRow;
        b1Base[np] = smb + 4u * (uint32_t)G1_B1W + (uint32_t)(n * 128);
        b3Base[np] = smb + 4u * (uint32_t)G1_B3W + (uint32_t)(n * 128);
    }

    float accG[2][4][4] = {};
    float accU[2][4][4] = {};

    auto compute_ks = [&](int s, int ks) {
        const uint32_t xoff = (uint32_t)(((ks * 2 + hi) ^ rx7) << 4);
        const uint32_t aS = (uint32_t)(s * G1_A_ST * 4) + xoff;
        const uint32_t bS = (uint32_t)(s * G1_B_ST * 4) + xoff;
        uint32_t af[2][4];
        #pragma unroll
        for (int mi = 0; mi < 2; ++mi)
            ldmx4(af[mi], aBase[mi] + aS);
        uint32_t b1f[4][2], b3f[4][2];
        #pragma unroll
        for (int np = 0; np < 2; ++np) {
            uint32_t q[4];
            ldmx4(q, b1Base[np] + bS);
            b1f[np * 2][0] = q[0]; b1f[np * 2 + 1][0] = q[1];
            b1f[np * 2][1] = q[2]; b1f[np * 2 + 1][1] = q[3];
            ldmx4(q, b3Base[np] + bS);
            b3f[np * 2][0] = q[0]; b3f[np * 2 + 1][0] = q[1];
            b3f[np * 2][1] = q[2]; b3f[np * 2 + 1][1] = q[3];
        }
        #pragma unroll
        for (int ni = 0; ni < 4; ++ni)
            #pragma unroll
            for (int mi = 0; mi < 2; ++mi) {
                mma_f16(accG[mi][ni], af[mi], b1f[ni]);
                mma_f16(accU[mi][ni], af[mi], b3f[ni]);
            }
    };

    const int KT = dH / TBK;   // 16
    cpaA(0, 0); cpa_commit();
    cpaA(1, 1); cpa_commit();
    ldgB(0, 0); stsB(0, 0);
    ldgB(0, 1); stsB(0, 1);
    ldgB(1, 0); stsB(1, 0);
    ldgB(1, 1); stsB(1, 1);
    cpa_wait0();
    __syncthreads();

    int s = 0, s2 = 2;
    for (int kt = 0; kt < KT; ++kt) {
        const bool more2 = (kt + 2 < KT);
        if (more2) { cpaA(kt + 2, s2); cpa_commit(); ldgB(kt + 2, 0); }

        compute_ks(s, 0);
        compute_ks(s, 1);

        if (more2) { stsB(s2, 0); ldgB(kt + 2, 1); }

        compute_ks(s, 2);
        compute_ks(s, 3);

        if (kt + 1 < KT) {
            if (more2) { stsB(s2, 1); cpa_wait1(); }
            else       { cpa_wait0(); }
            __syncthreads();
        }
        s = (s == 2) ? 0 : s + 1;
        s2 = (s2 == 2) ? 0 : s2 + 1;
    }

    #pragma unroll
    for (int mi = 0; mi < 2; ++mi) {
        int r0 = m0 + wm * 32 + mi * 16 + lr;
        int r1 = r0 + 8;
        #pragma unroll
        for (int ni = 0; ni < 4; ++ni) {
            int c = i0 + wn * 32 + ni * 8 + lc * 2;
            if (r0 < mEnd) {
                float g0 = accG[mi][ni][0], g1 = accG[mi][ni][1];
                float u0 = accU[mi][ni][0], u1 = accU[mi][ni][1];
                float h0 = g0 / (1.0f + __expf(-g0)) * u0;
                float h1 = g1 / (1.0f + __expf(-g1)) * u1;
                *(uint32_t*)&g_h[(size_t)r0 * dI + c] = packh2(h0, h1);
            }
            if (r1 < mEnd) {
                float g2 = accG[mi][ni][2], g3 = accG[mi][ni][3];
                float u2 = accU[mi][ni][2], u3 = accU[mi][ni][3];
                float h2 = g2 / (1.0f + __expf(-g2)) * u2;
                float h3 = g3 / (1.0f + __expf(-g3)) * u3;
                *(uint32_t*)&g_h[(size_t)r1 * dI + c] = packh2(h2, h3);
            }
        }
    }
}

// ============ GEMM2: CTA 128x128, warp 32x64, 3-stage — out += ew*(h@w2) ============
__global__ void __launch_bounds__(NTH, 2)
gemm2_mma(const float* __restrict__ ew,
          const float* __restrict__ w2,
          float* __restrict__ out) {
    if ((int)blockIdx.x >= g_ntiles) return;
    const int2 tile = g_tiles[blockIdx.x];
    const int e    = tile.x;
    const int m0   = tile.y;
    const int mEnd = g_off[e + 1];
    const int h0   = blockIdx.y * 128;

    extern __shared__ uint32_t dsm[];

    const int t = threadIdx.x;
    const int w = t >> 5, l = t & 31;
    const int wm = w & 3, wn = w >> 2;
    const int lr = l >> 2, lc = l & 3;
    const uint32_t smb = su32(dsm);
    const int lmRow = l & 15;
    const int rx7   = lmRow & 7;
    const int hi    = l >> 4;

    const float* w2e = w2 + (size_t)e * dI * dH + h0;

    uint32_t aDstW[4];
    const __half* aSrc[4];
    #pragma unroll
    for (int p = 0; p < 4; ++p) {
        int id = t + p * NTH;
        int row = id >> 3, qc = id & 7;
        aDstW[p] = (uint32_t)(row * 32 + ((qc ^ (row & 7)) * 4));
        int grow = (m0 + row < mEnd) ? (m0 + row) : m0;
        aSrc[p] = g_h + (size_t)grow * dI + qc * 8;
    }
    const int bN = t & 127, cI = t >> 7;   // cI 0..1
    const int bKb = cI * 16;
    const float* bSrc = w2e + (size_t)bKb * dH + bN;

    uint32_t uB[8];

    auto cpaA = [&](int kt, int s) {
        const int k0 = kt * TBK;
        #pragma unroll
        for (int p = 0; p < 4; ++p)
            cpa16(smb + 4u * (s * G2_A_ST + aDstW[p]), aSrc[p] + k0);
    };
    auto ldgB = [&](int kt, int h) {
        const float* pb = bSrc + (size_t)(kt * TBK + h * 32) * dH;
        #pragma unroll
        for (int jj = 0; jj < 8; ++jj)
            uB[jj] = packh2(pb[(size_t)(2 * jj) * dH], pb[(size_t)(2 * jj + 1) * dH]);
    };
    auto stsB = [&](int s, int h) {
        int c0 = 4 * h + 2 * cI;
        int off0 = bN * 32 + (((c0)     ^ (bN & 7)) * 4);
        int off1 = bN * 32 + (((c0 + 1) ^ (bN & 7)) * 4);
        *(uint4*)&dsm[G2_BW + s * G2_B_ST + off0] = make_uint4(uB[0], uB[1], uB[2], uB[3]);
        *(uint4*)&dsm[G2_BW + s * G2_B_ST + off1] = make_uint4(uB[4], uB[5], uB[6], uB[7]);
    };

    uint32_t aBase[2], bBase[4];
    #pragma unroll
    for (int mi = 0; mi < 2; ++mi)
        aBase[mi] = smb + (uint32_t)((wm * 32 + mi * 16 + lmRow) * 128);
    #pragma unroll
    for (int np = 0; np < 4; ++np) {
        int n = wn * 64 + np * 16 + lmRow;
        bBase[np] = smb + 4u * (uint32_t)G2_BW + (uint32_t)(n * 128);
    }

    float acc[2][8][4] = {};

    auto compute_ks = [&](int s, int ks) {
        const uint32_t xoff = (uint32_t)(((ks * 2 + hi) ^ rx7) << 4);
        const uint32_t aS = (uint32_t)(s * G2_A_ST * 4) + xoff;
        const uint32_t bS = (uint32_t)(s * G2_B_ST * 4) + xoff;
        uint32_t af[2][4];
        #pragma unroll
        for (int mi = 0; mi < 2; ++mi)
            ldmx4(af[mi], aBase[mi] + aS);
        uint32_t bf[8][2];
        #pragma unroll
        for (int np = 0; np < 4; ++np) {
            uint32_t q[4];
            ldmx4(q, bBase[np] + bS);
            bf[np * 2][0] = q[0]; bf[np * 2 + 1][0] = q[1];
            bf[np * 2][1] = q[2]; bf[np * 2 + 1][1] = q[3];
        }
        #pragma unroll
        for (int ni = 0; ni < 8; ++ni)
            #pragma unroll
            for (int mi = 0; mi < 2; ++mi)
                mma_f16(acc[mi][ni], af[mi], bf[ni]);
    };

    const int KT = dI / TBK;   // 64
    cpaA(0, 0); cpa_commit();
    cpaA(1, 1); cpa_commit();
    ldgB(0, 0); stsB(0, 0);
    ldgB(0, 1); stsB(0, 1);
    ldgB(1, 0); stsB(1, 0);
    ldgB(1, 1); stsB(1, 1);
    cpa_wait0();
    __syncthreads();

    int s = 0, s2 = 2;
    for (int kt = 0; kt < KT; ++kt) {
        const bool more2 = (kt + 2 < KT);
        if (more2) { cpaA(kt + 2, s2); cpa_commit(); ldgB(kt + 2, 0); }

        compute_ks(s, 0);
        compute_ks(s, 1);

        if (more2) { stsB(s2, 0); ldgB(kt + 2, 1); }

        compute_ks(s, 2);
        compute_ks(s, 3);

        if (kt + 1 < KT) {
            if (more2) { stsB(s2, 1); cpa_wait1(); }
            else       { cpa_wait0(); }
            __syncthreads();
        }
        s = (s == 2) ? 0 : s + 1;
        s2 = (s2 == 2) ? 0 : s2 + 1;
    }

    #pragma unroll
    for (int mi = 0; mi < 2; ++mi) {
        int r0 = m0 + wm * 32 + mi * 16 + lr;
        int r1 = r0 + 8;
        int tk0 = -1, tk1 = -1;
        float wg0 = 0.0f, wg1 = 0.0f;
        if (r0 < mEnd) { int p = g_pairs[r0]; wg0 = ew[p]; tk0 = p / dK; }
        if (r1 < mEnd) { int p = g_pairs[r1]; wg1 = ew[p]; tk1 = p / dK; }
        #pragma unroll
        for (int ni = 0; ni < 8; ++ni) {
            int c = h0 + wn * 64 + ni * 8 + lc * 2;
            if (tk0 >= 0) {
                atomicAdd(&out[(size_t)tk0 * dH + c],     wg0 * acc[mi][ni][0]);
                atomicAdd(&out[(size_t)tk0 * dH + c + 1], wg0 * acc[mi][ni][1]);
            }
            if (tk1 >= 0) {
                atomicAdd(&out[(size_t)tk1 * dH + c],     wg1 * acc[mi][ni][2]);
                atomicAdd(&out[(size_t)tk1 * dH + c + 1], wg1 * acc[mi][ni][3]);
            }
        }
    }
}

extern "C" void kernel_launch(void* const* d_in, const int* in_sizes, int n_in,
                              void* d_out, int out_size) {
    const float* x   = (const float*)d_in[0];
    const int*   idx = (const int*)  d_in[1];
    const float* ew  = (const float*)d_in[2];
    const float* w1  = (const float*)d_in[3];
    const float* w2  = (const float*)d_in[4];
    const float* w3  = (const float*)d_in[5];
    float* out = (float*)d_out;

    const int smem1 = G1_SMEM_W * 4;   // 98304 B
    const int smem2 = G2_SMEM_W * 4;   // 98304 B
    cudaFuncSetAttribute(gemm1_mma, cudaFuncAttributeMaxDynamicSharedMemorySize, smem1);
    cudaFuncSetAttribute(gemm2_mma, cudaFuncAttributeMaxDynamicSharedMemorySize, smem2);

    route_kernel<<<1, 256>>>(idx);
    cvt_x_kernel<<<(dN * dH / 4 + 255) / 256, 256>>>(x);
    zero_out_kernel<<<(dN * dH / 4 + 255) / 256, 256>>>(out);
    dim3 g1(MAXTILES, dI / 64, 1);    // 40 x 64
    gemm1_mma<<<g1, NTH, smem1>>>(w1, w3);
    dim3 g2(MAXTILES, dH / 128, 1);   // 40 x 8
    gemm2_mma<<<g2, NTH, smem2>>>(ew, w2, out);
}